// round 1
// baseline (speedup 1.0000x reference)
#include <cuda_runtime.h>
#include <math.h>

// Problem constants
#define MM 1024
#define NN 4096
#define DD 128
#define HH 32
#define PP 4096
#define KVLEN 5120   // PP + MM

// Scratch (allocation-free rule: __device__ globals)
__device__ float g_Xn[MM * NN];
__device__ float g_q[MM * NN];
__device__ float g_k[MM * NN];
__device__ float g_v[MM * NN];

// ---------------------------------------------------------------------------
// RMSNorm over rows of X [1024, 4096]
// ---------------------------------------------------------------------------
__global__ __launch_bounds__(256) void rmsnorm_x_kernel(const float* __restrict__ X,
                                                        float* __restrict__ Y) {
    int row = blockIdx.x;
    const float4* x4 = (const float4*)(X + (size_t)row * NN);
    float4* y4 = (float4*)(Y + (size_t)row * NN);
    float4 v[4];
    float ss = 0.f;
#pragma unroll
    for (int i = 0; i < 4; i++) {
        v[i] = x4[threadIdx.x + i * 256];
        ss += v[i].x * v[i].x + v[i].y * v[i].y + v[i].z * v[i].z + v[i].w * v[i].w;
    }
#pragma unroll
    for (int o = 16; o; o >>= 1) ss += __shfl_xor_sync(0xffffffffu, ss, o);
    __shared__ float wsum[8];
    int warp = threadIdx.x >> 5, lane = threadIdx.x & 31;
    if (lane == 0) wsum[warp] = ss;
    __syncthreads();
    float tot = 0.f;
#pragma unroll
    for (int w = 0; w < 8; w++) tot += wsum[w];
    float s = rsqrtf(tot * (1.0f / (float)NN));
#pragma unroll
    for (int i = 0; i < 4; i++) {
        v[i].x *= s; v[i].y *= s; v[i].z *= s; v[i].w *= s;
        y4[threadIdx.x + i * 256] = v[i];
    }
}

// ---------------------------------------------------------------------------
// SGEMM: C[1024,4096] = A[1024,4096] @ B[4096,4096], all row-major fp32.
// 128x128 block tile, BK=8, 8x8 per thread, 256 threads.
// ---------------------------------------------------------------------------
__global__ __launch_bounds__(256) void sgemm128(const float* __restrict__ A,
                                                const float* __restrict__ B,
                                                float* __restrict__ C) {
    __shared__ float As[8][128];
    __shared__ float Bs[8][128];
    const int bn = blockIdx.x, bm = blockIdx.y;
    const int tid = threadIdx.x;
    const int tr = tid >> 4, tc = tid & 15;
    const int arow = tid >> 1, acol = (tid & 1) * 4;
    const int brow = tid >> 5, bcol = (tid & 31) * 4;
    const float* Ap = A + (size_t)(bm * 128 + arow) * NN + acol;
    const float* Bp = B + (size_t)brow * NN + bn * 128 + bcol;

    float acc[8][8];
#pragma unroll
    for (int i = 0; i < 8; i++)
#pragma unroll
        for (int j = 0; j < 8; j++) acc[i][j] = 0.f;

    for (int kk = 0; kk < NN; kk += 8) {
        float4 a = *(const float4*)(Ap + kk);
        float4 b = *(const float4*)(Bp + (size_t)kk * NN);
        As[acol + 0][arow] = a.x;
        As[acol + 1][arow] = a.y;
        As[acol + 2][arow] = a.z;
        As[acol + 3][arow] = a.w;
        *(float4*)&Bs[brow][bcol] = b;
        __syncthreads();
#pragma unroll
        for (int k = 0; k < 8; k++) {
            float ra[8], rb[8];
            *(float4*)&ra[0] = *(const float4*)&As[k][tr * 8];
            *(float4*)&ra[4] = *(const float4*)&As[k][tr * 8 + 4];
            *(float4*)&rb[0] = *(const float4*)&Bs[k][tc * 8];
            *(float4*)&rb[4] = *(const float4*)&Bs[k][tc * 8 + 4];
#pragma unroll
            for (int i = 0; i < 8; i++)
#pragma unroll
                for (int j = 0; j < 8; j++) acc[i][j] += ra[i] * rb[j];
        }
        __syncthreads();
    }
#pragma unroll
    for (int i = 0; i < 8; i++) {
        float* Cp = C + (size_t)(bm * 128 + tr * 8 + i) * NN + bn * 128 + tc * 8;
        float4 o0 = make_float4(acc[i][0], acc[i][1], acc[i][2], acc[i][3]);
        float4 o1 = make_float4(acc[i][4], acc[i][5], acc[i][6], acc[i][7]);
        *(float4*)Cp = o0;
        *(float4*)(Cp + 4) = o1;
    }
}

// ---------------------------------------------------------------------------
// Per-head RMSNorm over D=128 for q and k (in place). One warp per row.
// ---------------------------------------------------------------------------
__global__ __launch_bounds__(256) void qknorm_kernel(float* __restrict__ q,
                                                     float* __restrict__ k) {
    int gw = (int)((blockIdx.x * blockDim.x + threadIdx.x) >> 5);
    int lane = threadIdx.x & 31;
    float* base = (gw < MM * HH) ? q : k;
    int row = (gw < MM * HH) ? gw : gw - MM * HH;
    float4* p = (float4*)(base + (size_t)row * DD);
    float4 a = p[lane];
    float ss = a.x * a.x + a.y * a.y + a.z * a.z + a.w * a.w;
#pragma unroll
    for (int o = 16; o; o >>= 1) ss += __shfl_xor_sync(0xffffffffu, ss, o);
    float s = rsqrtf(ss * (1.0f / (float)DD));
    a.x *= s; a.y *= s; a.z *= s; a.w *= s;
    p[lane] = a;
}

// ---------------------------------------------------------------------------
// Flash attention, fp32, non-causal, sm_scale = 1.0.
// Block = (m_tile of 64 queries, head). 80 kv tiles of 64.
// smem: Qs[64][128], KsT[128][68] (padded transpose), Vs[64][128],
//       Ss[64][65] (padded), stats.
// ---------------------------------------------------------------------------
#define KST_STRIDE 68
#define SS_STRIDE 65
#define ATT_SMEM_FLOATS (64 * 128 + 128 * KST_STRIDE + 64 * 128 + 64 * SS_STRIDE + 3 * 64)
#define ATT_SMEM_BYTES (ATT_SMEM_FLOATS * 4)

__global__ __launch_bounds__(256) void attn_kernel(const float* __restrict__ qn,
                                                   const float* __restrict__ kn,
                                                   const float* __restrict__ vp,
                                                   const float* __restrict__ cacheK,
                                                   const float* __restrict__ cacheV,
                                                   float* __restrict__ out) {
    extern __shared__ float sm[];
    float* Qs = sm;                         // [64][128]
    float* KsT = Qs + 64 * 128;             // [128][KST_STRIDE]
    float* Vs = KsT + 128 * KST_STRIDE;     // [64][128]
    float* Ss = Vs + 64 * 128;              // [64][SS_STRIDE]
    float* m_i = Ss + 64 * SS_STRIDE;       // [64]
    float* l_i = m_i + 64;                  // [64]
    float* sc = l_i + 64;                   // [64]

    const int tid = threadIdx.x;
    const int mt = blockIdx.x, h = blockIdx.y;
    const int tr = tid >> 4;   // 0..15 : S rows tr*4.. , O rows tr*4..
    const int tc = tid & 15;   // 0..15 : S cols tc*4.. , O cols tc*8..

    // Load Q tile (rows mt*64.., cols h*128..)
#pragma unroll
    for (int i = 0; i < 8; i++) {
        int idx = tid + i * 256;            // 0..2047 float4s
        int r = idx >> 5, c4 = idx & 31;
        ((float4*)Qs)[r * 32 + c4] =
            *(const float4*)(qn + (size_t)(mt * 64 + r) * NN + h * DD + c4 * 4);
    }
    if (tid < 64) { m_i[tid] = -INFINITY; l_i[tid] = 0.f; }

    float O[4][8];
#pragma unroll
    for (int i = 0; i < 4; i++)
#pragma unroll
        for (int c = 0; c < 8; c++) O[i][c] = 0.f;
    __syncthreads();

    for (int t = 0; t < KVLEN / 64; t++) {
        const int kvbase = t * 64;
        const bool incache = (kvbase < PP);
        // Load K (transposed, padded) and V tiles
#pragma unroll
        for (int i = 0; i < 8; i++) {
            int idx = tid + i * 256;
            int r = idx >> 5, c4 = idx & 31;
            const float *ksrc, *vsrc;
            if (incache) {
                size_t off = ((size_t)h * PP + kvbase + r) * DD + c4 * 4;
                ksrc = cacheK + off;
                vsrc = cacheV + off;
            } else {
                size_t off = (size_t)(kvbase - PP + r) * NN + h * DD + c4 * 4;
                ksrc = kn + off;
                vsrc = vp + off;
            }
            float4 kv4 = *(const float4*)ksrc;
            KsT[(c4 * 4 + 0) * KST_STRIDE + r] = kv4.x;
            KsT[(c4 * 4 + 1) * KST_STRIDE + r] = kv4.y;
            KsT[(c4 * 4 + 2) * KST_STRIDE + r] = kv4.z;
            KsT[(c4 * 4 + 3) * KST_STRIDE + r] = kv4.w;
            ((float4*)Vs)[r * 32 + c4] = *(const float4*)vsrc;
        }
        __syncthreads();

        // S = Q @ K^T  (each thread: 4x4 tile)
        float s[4][4];
#pragma unroll
        for (int i = 0; i < 4; i++)
#pragma unroll
            for (int j = 0; j < 4; j++) s[i][j] = 0.f;
#pragma unroll 8
        for (int k = 0; k < DD; k++) {
            float a0 = Qs[(tr * 4 + 0) * 128 + k];
            float a1 = Qs[(tr * 4 + 1) * 128 + k];
            float a2 = Qs[(tr * 4 + 2) * 128 + k];
            float a3 = Qs[(tr * 4 + 3) * 128 + k];
            float4 b = *(const float4*)&KsT[k * KST_STRIDE + tc * 4];
            s[0][0] += a0 * b.x; s[0][1] += a0 * b.y; s[0][2] += a0 * b.z; s[0][3] += a0 * b.w;
            s[1][0] += a1 * b.x; s[1][1] += a1 * b.y; s[1][2] += a1 * b.z; s[1][3] += a1 * b.w;
            s[2][0] += a2 * b.x; s[2][1] += a2 * b.y; s[2][2] += a2 * b.z; s[2][3] += a2 * b.w;
            s[3][0] += a3 * b.x; s[3][1] += a3 * b.y; s[3][2] += a3 * b.z; s[3][3] += a3 * b.w;
        }
#pragma unroll
        for (int i = 0; i < 4; i++)
#pragma unroll
            for (int j = 0; j < 4; j++)
                Ss[(tr * 4 + i) * SS_STRIDE + tc * 4 + j] = s[i][j];
        __syncthreads();

        // Online softmax: 4 threads per row (16 cols each)
        {
            int row = tid >> 2, seg = tid & 3;
            float mx = -INFINITY;
#pragma unroll
            for (int c = 0; c < 16; c++)
                mx = fmaxf(mx, Ss[row * SS_STRIDE + seg * 16 + c]);
            mx = fmaxf(mx, __shfl_xor_sync(0xffffffffu, mx, 1));
            mx = fmaxf(mx, __shfl_xor_sync(0xffffffffu, mx, 2));
            float mprev = m_i[row];
            float mnew = fmaxf(mprev, mx);
            float lsum = 0.f;
#pragma unroll
            for (int c = 0; c < 16; c++) {
                float p = __expf(Ss[row * SS_STRIDE + seg * 16 + c] - mnew);
                Ss[row * SS_STRIDE + seg * 16 + c] = p;
                lsum += p;
            }
            lsum += __shfl_xor_sync(0xffffffffu, lsum, 1);
            lsum += __shfl_xor_sync(0xffffffffu, lsum, 2);
            if (seg == 0) {
                float f = __expf(mprev - mnew);
                sc[row] = f;
                m_i[row] = mnew;
                l_i[row] = l_i[row] * f + lsum;
            }
        }
        __syncthreads();

        // O = O*scale + P @ V  (each thread: 4 rows x 8 cols of O)
#pragma unroll
        for (int i = 0; i < 4; i++) {
            float f = sc[tr * 4 + i];
#pragma unroll
            for (int c = 0; c < 8; c++) O[i][c] *= f;
        }
#pragma unroll 4
        for (int j = 0; j < 64; j++) {
            float p0 = Ss[(tr * 4 + 0) * SS_STRIDE + j];
            float p1 = Ss[(tr * 4 + 1) * SS_STRIDE + j];
            float p2 = Ss[(tr * 4 + 2) * SS_STRIDE + j];
            float p3 = Ss[(tr * 4 + 3) * SS_STRIDE + j];
            float4 v0 = ((const float4*)Vs)[j * 32 + tc * 2];
            float4 v1 = ((const float4*)Vs)[j * 32 + tc * 2 + 1];
            O[0][0] += p0 * v0.x; O[0][1] += p0 * v0.y; O[0][2] += p0 * v0.z; O[0][3] += p0 * v0.w;
            O[0][4] += p0 * v1.x; O[0][5] += p0 * v1.y; O[0][6] += p0 * v1.z; O[0][7] += p0 * v1.w;
            O[1][0] += p1 * v0.x; O[1][1] += p1 * v0.y; O[1][2] += p1 * v0.z; O[1][3] += p1 * v0.w;
            O[1][4] += p1 * v1.x; O[1][5] += p1 * v1.y; O[1][6] += p1 * v1.z; O[1][7] += p1 * v1.w;
            O[2][0] += p2 * v0.x; O[2][1] += p2 * v0.y; O[2][2] += p2 * v0.z; O[2][3] += p2 * v0.w;
            O[2][4] += p2 * v1.x; O[2][5] += p2 * v1.y; O[2][6] += p2 * v1.z; O[2][7] += p2 * v1.w;
            O[3][0] += p3 * v0.x; O[3][1] += p3 * v0.y; O[3][2] += p3 * v0.z; O[3][3] += p3 * v0.w;
            O[3][4] += p3 * v1.x; O[3][5] += p3 * v1.y; O[3][6] += p3 * v1.z; O[3][7] += p3 * v1.w;
        }
        __syncthreads();
    }

    // Epilogue: divide by l and store
#pragma unroll
    for (int i = 0; i < 4; i++) {
        float inv = 1.0f / l_i[tr * 4 + i];
        float* dst = out + (size_t)(mt * 64 + tr * 4 + i) * NN + h * DD + tc * 8;
        float4 o0 = make_float4(O[i][0] * inv, O[i][1] * inv, O[i][2] * inv, O[i][3] * inv);
        float4 o1 = make_float4(O[i][4] * inv, O[i][5] * inv, O[i][6] * inv, O[i][7] * inv);
        *(float4*)dst = o0;
        *(float4*)(dst + 4) = o1;
    }
}

// ---------------------------------------------------------------------------
extern "C" void kernel_launch(void* const* d_in, const int* in_sizes, int n_in,
                              void* d_out, int out_size) {
    const float* X  = (const float*)d_in[0];
    const float* Wq = (const float*)d_in[1];
    const float* Wk = (const float*)d_in[2];
    const float* Wv = (const float*)d_in[3];
    const float* cK = (const float*)d_in[4];
    const float* cV = (const float*)d_in[5];
    float* out = (float*)d_out;

    float *Xn, *q, *k, *v;
    cudaGetSymbolAddress((void**)&Xn, g_Xn);
    cudaGetSymbolAddress((void**)&q, g_q);
    cudaGetSymbolAddress((void**)&k, g_k);
    cudaGetSymbolAddress((void**)&v, g_v);

    rmsnorm_x_kernel<<<MM, 256>>>(X, Xn);

    dim3 ggrid(NN / 128, MM / 128);
    sgemm128<<<ggrid, 256>>>(Xn, Wq, q);
    sgemm128<<<ggrid, 256>>>(Xn, Wk, k);
    sgemm128<<<ggrid, 256>>>(Xn, Wv, v);

    qknorm_kernel<<<(2 * MM * HH * 32) / 256, 256>>>(q, k);

    cudaFuncSetAttribute(attn_kernel, cudaFuncAttributeMaxDynamicSharedMemorySize,
                         ATT_SMEM_BYTES);
    attn_kernel<<<dim3(MM / 64, HH), 256, ATT_SMEM_BYTES>>>(q, k, v, cK, cV, out);
}

// round 4
// speedup vs baseline: 2.6975x; 2.6975x over previous
#include <cuda_runtime.h>
#include <cuda_bf16.h>
#include <math.h>
#include <stdint.h>

typedef __nv_bfloat16 bf16;

// Problem constants
#define MM 1024
#define NN 4096
#define DD 128
#define HH 32
#define PP 4096
#define KVLEN 5120   // PP + MM
#define MN (MM * NN)

// ---------------------------------------------------------------------------
// Scratch (allocation-free rule: __device__ globals)
// ---------------------------------------------------------------------------
__device__ float g_Xn[MN];
__device__ float g_qkv[3ull * MN];                   // q | k | v
__device__ bf16 g_Xhi[MN];
__device__ bf16 g_Xlo[MN];
__device__ bf16 g_Wthi[3ull * NN * NN];              // W transposed [n][k], hi
__device__ bf16 g_Wtlo[3ull * NN * NN];
__device__ bf16 g_Qhi[MN];
__device__ bf16 g_Qlo[MN];
__device__ bf16 g_Khi[(size_t)HH * KVLEN * DD];      // [h][kv][d]
__device__ bf16 g_Klo[(size_t)HH * KVLEN * DD];
__device__ bf16 g_Vthi[(size_t)HH * DD * KVLEN];     // [h][d][kv]
__device__ bf16 g_Vtlo[(size_t)HH * DD * KVLEN];
__device__ float g_S[(size_t)HH * MM * KVLEN];       // logits
__device__ bf16 g_Phi[(size_t)HH * MM * KVLEN];
__device__ bf16 g_Plo[(size_t)HH * MM * KVLEN];

// ---------------------------------------------------------------------------
// Helpers
// ---------------------------------------------------------------------------
__device__ __forceinline__ uint32_t smem_u32(const void* p) {
    uint32_t a;
    asm("{ .reg .u64 t; cvta.to.shared.u64 t, %1; cvt.u32.u64 %0, t; }" : "=r"(a) : "l"(p));
    return a;
}
__device__ __forceinline__ void ldsm_x4(uint32_t* r, uint32_t addr) {
    asm volatile("ldmatrix.sync.aligned.m8n8.x4.shared.b16 {%0,%1,%2,%3}, [%4];"
                 : "=r"(r[0]), "=r"(r[1]), "=r"(r[2]), "=r"(r[3]) : "r"(addr));
}
__device__ __forceinline__ void ldsm_x2(uint32_t* r, uint32_t addr) {
    asm volatile("ldmatrix.sync.aligned.m8n8.x2.shared.b16 {%0,%1}, [%2];"
                 : "=r"(r[0]), "=r"(r[1]) : "r"(addr));
}
#define MMA16816(d, a, b)                                              \
    asm volatile(                                                      \
        "mma.sync.aligned.m16n8k16.row.col.f32.bf16.bf16.f32 "         \
        "{%0,%1,%2,%3}, {%4,%5,%6,%7}, {%8,%9}, {%0,%1,%2,%3};"        \
        : "+f"((d)[0]), "+f"((d)[1]), "+f"((d)[2]), "+f"((d)[3])       \
        : "r"((a)[0]), "r"((a)[1]), "r"((a)[2]), "r"((a)[3]),          \
          "r"((b)[0]), "r"((b)[1]))

__device__ __forceinline__ void split2(float x, bf16& h, bf16& l) {
    h = __float2bfloat16(x);
    l = __float2bfloat16(x - __bfloat162float(h));
}

// ---------------------------------------------------------------------------
// RMSNorm over rows of X [1024, 4096]
// ---------------------------------------------------------------------------
__global__ __launch_bounds__(256) void rmsnorm_x_kernel(const float* __restrict__ X,
                                                        float* __restrict__ Y) {
    int row = blockIdx.x;
    const float4* x4 = (const float4*)(X + (size_t)row * NN);
    float4* y4 = (float4*)(Y + (size_t)row * NN);
    float4 v[4];
    float ss = 0.f;
#pragma unroll
    for (int i = 0; i < 4; i++) {
        v[i] = x4[threadIdx.x + i * 256];
        ss += v[i].x * v[i].x + v[i].y * v[i].y + v[i].z * v[i].z + v[i].w * v[i].w;
    }
#pragma unroll
    for (int o = 16; o; o >>= 1) ss += __shfl_xor_sync(0xffffffffu, ss, o);
    __shared__ float wsum[8];
    int warp = threadIdx.x >> 5, lane = threadIdx.x & 31;
    if (lane == 0) wsum[warp] = ss;
    __syncthreads();
    float tot = 0.f;
#pragma unroll
    for (int w = 0; w < 8; w++) tot += wsum[w];
    float s = rsqrtf(tot * (1.0f / (float)NN));
#pragma unroll
    for (int i = 0; i < 4; i++) {
        v[i].x *= s; v[i].y *= s; v[i].z *= s; v[i].w *= s;
        y4[threadIdx.x + i * 256] = v[i];
    }
}

// ---------------------------------------------------------------------------
// Generic fp32 -> bf16 hi/lo split (vectorized x4)
// ---------------------------------------------------------------------------
__global__ __launch_bounds__(256) void split_kernel(const float* __restrict__ src,
                                                    bf16* __restrict__ hi,
                                                    bf16* __restrict__ lo) {
    size_t i = ((size_t)blockIdx.x * 256 + threadIdx.x) * 4;
    float4 v = *(const float4*)(src + i);
    bf16 h0, h1, h2, h3, l0, l1, l2, l3;
    split2(v.x, h0, l0); split2(v.y, h1, l1);
    split2(v.z, h2, l2); split2(v.w, h3, l3);
    *(__nv_bfloat162*)(hi + i)     = __nv_bfloat162(h0, h1);
    *(__nv_bfloat162*)(hi + i + 2) = __nv_bfloat162(h2, h3);
    *(__nv_bfloat162*)(lo + i)     = __nv_bfloat162(l0, l1);
    *(__nv_bfloat162*)(lo + i + 2) = __nv_bfloat162(l2, l3);
}

// ---------------------------------------------------------------------------
// Transpose + split W [K, N] fp32 -> Wt hi/lo bf16 [N, K]
// ---------------------------------------------------------------------------
__global__ __launch_bounds__(256) void wsplit_kernel(const float* __restrict__ W,
                                                     bf16* __restrict__ hi,
                                                     bf16* __restrict__ lo) {
    __shared__ float t[32][33];
    int tx = threadIdx.x & 31, ty = threadIdx.x >> 5;
    int n0 = blockIdx.x * 32, k0 = blockIdx.y * 32;
#pragma unroll
    for (int i = 0; i < 4; i++)
        t[ty + i * 8][tx] = W[(size_t)(k0 + ty + i * 8) * NN + n0 + tx];
    __syncthreads();
#pragma unroll
    for (int i = 0; i < 4; i++) {
        float v = t[tx][ty + i * 8];
        bf16 h, l;
        split2(v, h, l);
        size_t off = (size_t)(n0 + ty + i * 8) * NN + k0 + tx;
        hi[off] = h;
        lo[off] = l;
    }
}

// ---------------------------------------------------------------------------
// Per-head RMSNorm over D=128 for q and k (in place). One warp per row.
// ---------------------------------------------------------------------------
__global__ __launch_bounds__(256) void qknorm_kernel(float* __restrict__ q,
                                                     float* __restrict__ k) {
    int gw = (int)((blockIdx.x * blockDim.x + threadIdx.x) >> 5);
    int lane = threadIdx.x & 31;
    float* base = (gw < MM * HH) ? q : k;
    int row = (gw < MM * HH) ? gw : gw - MM * HH;
    float4* p = (float4*)(base + (size_t)row * DD);
    float4 a = p[lane];
    float ss = a.x * a.x + a.y * a.y + a.z * a.z + a.w * a.w;
#pragma unroll
    for (int o = 16; o; o >>= 1) ss += __shfl_xor_sync(0xffffffffu, ss, o);
    float s = rsqrtf(ss * (1.0f / (float)DD));
    a.x *= s; a.y *= s; a.z *= s; a.w *= s;
    p[lane] = a;
}

// ---------------------------------------------------------------------------
// Build K cache (combined) hi/lo: [h][kv][d], kv<PP from cache_K else k proj
// ---------------------------------------------------------------------------
__global__ __launch_bounds__(256) void build_khl(const float* __restrict__ cacheK,
                                                 const float* __restrict__ kproj,
                                                 bf16* __restrict__ Kh,
                                                 bf16* __restrict__ Kl) {
    size_t e = ((size_t)blockIdx.x * 256 + threadIdx.x) * 4;
    int h = (int)(e / ((size_t)KVLEN * DD));
    int rem = (int)(e % ((size_t)KVLEN * DD));
    int r = rem / DD, c = rem % DD;
    const float* src = (r < PP)
        ? cacheK + (((size_t)h * PP + r) * DD + c)
        : kproj + ((size_t)(r - PP) * NN + h * DD + c);
    float4 v = *(const float4*)src;
    bf16 h0, h1, h2, h3, l0, l1, l2, l3;
    split2(v.x, h0, l0); split2(v.y, h1, l1);
    split2(v.z, h2, l2); split2(v.w, h3, l3);
    *(__nv_bfloat162*)(Kh + e)     = __nv_bfloat162(h0, h1);
    *(__nv_bfloat162*)(Kh + e + 2) = __nv_bfloat162(h2, h3);
    *(__nv_bfloat162*)(Kl + e)     = __nv_bfloat162(l0, l1);
    *(__nv_bfloat162*)(Kl + e + 2) = __nv_bfloat162(l2, l3);
}

// ---------------------------------------------------------------------------
// Build V^T hi/lo: [h][d][kv] (transposed), sources cache_V and v proj
// grid (KVLEN/32, DD/32, HH), block 256 (32x8)
// ---------------------------------------------------------------------------
__global__ __launch_bounds__(256) void build_vt(const float* __restrict__ cacheV,
                                                const float* __restrict__ vproj,
                                                bf16* __restrict__ Vh,
                                                bf16* __restrict__ Vl) {
    __shared__ float t[32][33];
    int tx = threadIdx.x & 31, ty = threadIdx.x >> 5;
    int kv0 = blockIdx.x * 32, d0 = blockIdx.y * 32, h = blockIdx.z;
#pragma unroll
    for (int i = 0; i < 4; i++) {
        int r = kv0 + ty + i * 8;
        int c = d0 + tx;
        float v = (r < PP)
            ? cacheV[((size_t)h * PP + r) * DD + c]
            : vproj[(size_t)(r - PP) * NN + h * DD + c];
        t[ty + i * 8][tx] = v;
    }
    __syncthreads();
#pragma unroll
    for (int i = 0; i < 4; i++) {
        int d = d0 + ty + i * 8;
        float v = t[tx][ty + i * 8];
        bf16 hh, ll;
        split2(v, hh, ll);
        size_t off = ((size_t)h * DD + d) * KVLEN + kv0 + tx;
        Vh[off] = hh;
        Vl[off] = ll;
    }
}

// ---------------------------------------------------------------------------
// bf16x3 GEMM on tensor cores (mma.sync m16n8k16).
// C[M,N] = A[M,K] @ B[N,K]^T with A = Ah+Al, B = Bh+Bl,
// C = Ah*Bh + Ah*Bl + Al*Bh.  BM=128 fixed, 256 threads = 2x4 warps,
// warp tile 64 x WN.  Batch via blockIdx.z with element strides sA/sB/sC.
// ---------------------------------------------------------------------------
template <int BN, int WN>
__global__ __launch_bounds__(256, 1) void gemm3(
    const bf16* __restrict__ Ah, const bf16* __restrict__ Al,
    const bf16* __restrict__ Bh, const bf16* __restrict__ Bl,
    float* __restrict__ C, int K, int lda, int ldb, int ldc,
    long long sA, long long sB, long long sC) {
    constexpr int BM = 128;
    constexpr int NFR = WN / 8;
    constexpr int PADB = 80;   // bytes per padded smem row (32 bf16 + 8 pad)
    extern __shared__ char smraw[];
    char* sAh = smraw;
    char* sAl = sAh + BM * PADB;
    char* sBh = sAl + BM * PADB;
    char* sBl = sBh + BN * PADB;

    const int tid = threadIdx.x;
    const int lane = tid & 31, wid = tid >> 5;
    const int wr = wid >> 2, wc = wid & 3;
    const int m0 = blockIdx.y * BM, n0 = blockIdx.x * BN;
    Ah += (long long)blockIdx.z * sA;
    Al += (long long)blockIdx.z * sA;
    Bh += (long long)blockIdx.z * sB;
    Bl += (long long)blockIdx.z * sB;
    C += (long long)blockIdx.z * sC;

    float acc[4][NFR][4];
#pragma unroll
    for (int f = 0; f < 4; f++)
#pragma unroll
        for (int j = 0; j < NFR; j++)
#pragma unroll
            for (int x = 0; x < 4; x++) acc[f][j][x] = 0.f;

    const uint32_t aH = smem_u32(sAh), aL = smem_u32(sAl);
    const uint32_t bH = smem_u32(sBh), bL = smem_u32(sBl);
    const uint32_t aoff = (uint32_t)((wr * 64 + (lane & 15)) * PADB + (lane >> 4) * 16);
    const uint32_t boff = (uint32_t)((wc * WN + (lane & 7)) * PADB + ((lane >> 3) & 1) * 16);

    for (int kc = 0; kc < K; kc += 32) {
        // Fill smem tiles
        const bf16* pAh = Ah + (size_t)m0 * lda + kc;
        const bf16* pAl = Al + (size_t)m0 * lda + kc;
#pragma unroll
        for (int i = tid; i < BM * 4; i += 256) {
            int r = i >> 2, cb = (i & 3) * 16;
            *(float4*)(sAh + r * PADB + cb) = *(const float4*)((const char*)(pAh + (size_t)r * lda) + cb);
            *(float4*)(sAl + r * PADB + cb) = *(const float4*)((const char*)(pAl + (size_t)r * lda) + cb);
        }
        const bf16* pBh = Bh + (size_t)n0 * ldb + kc;
        const bf16* pBl = Bl + (size_t)n0 * ldb + kc;
#pragma unroll
        for (int i = tid; i < BN * 4; i += 256) {
            int r = i >> 2, cb = (i & 3) * 16;
            *(float4*)(sBh + r * PADB + cb) = *(const float4*)((const char*)(pBh + (size_t)r * ldb) + cb);
            *(float4*)(sBl + r * PADB + cb) = *(const float4*)((const char*)(pBl + (size_t)r * ldb) + cb);
        }
        __syncthreads();

#pragma unroll
        for (int ks = 0; ks < 2; ks++) {
            uint32_t ah[4][4], al[4][4];
#pragma unroll
            for (int f = 0; f < 4; f++) {
                uint32_t off = aoff + f * 16 * PADB + ks * 32;
                ldsm_x4(ah[f], aH + off);
                ldsm_x4(al[f], aL + off);
            }
#pragma unroll
            for (int j = 0; j < NFR; j++) {
                uint32_t off = boff + j * 8 * PADB + ks * 32;
                uint32_t bh[2], bl[2];
                ldsm_x2(bh, bH + off);
                ldsm_x2(bl, bL + off);
#pragma unroll
                for (int f = 0; f < 4; f++) {
                    MMA16816(acc[f][j], ah[f], bh);
                    MMA16816(acc[f][j], ah[f], bl);
                    MMA16816(acc[f][j], al[f], bh);
                }
            }
        }
        __syncthreads();
    }

    // Epilogue
#pragma unroll
    for (int f = 0; f < 4; f++) {
        int row = m0 + wr * 64 + f * 16 + (lane >> 2);
#pragma unroll
        for (int j = 0; j < NFR; j++) {
            int col = n0 + wc * WN + j * 8 + (lane & 3) * 2;
            *(float2*)(C + (size_t)row * ldc + col) = make_float2(acc[f][j][0], acc[f][j][1]);
            *(float2*)(C + (size_t)(row + 8) * ldc + col) = make_float2(acc[f][j][2], acc[f][j][3]);
        }
    }
}

// ---------------------------------------------------------------------------
// Row softmax over KVLEN=5120, writes P = softmax(S) scaled by 1/l as hi/lo
// One block (256 threads) per row; 20 elements per thread.
// ---------------------------------------------------------------------------
__global__ __launch_bounds__(256) void softmax_kernel(const float* __restrict__ S,
                                                      bf16* __restrict__ Ph,
                                                      bf16* __restrict__ Pl) {
    __shared__ float red[8];
    size_t row = blockIdx.x;
    const float* s = S + row * KVLEN;
    int tid = threadIdx.x, lane = tid & 31, wid = tid >> 5;
    float v[20];
    float mx = -INFINITY;
#pragma unroll
    for (int i = 0; i < 20; i++) {
        v[i] = s[tid + i * 256];
        mx = fmaxf(mx, v[i]);
    }
#pragma unroll
    for (int o = 16; o; o >>= 1) mx = fmaxf(mx, __shfl_xor_sync(0xffffffffu, mx, o));
    if (lane == 0) red[wid] = mx;
    __syncthreads();
    float m = -INFINITY;
#pragma unroll
    for (int w = 0; w < 8; w++) m = fmaxf(m, red[w]);
    __syncthreads();

    float l = 0.f;
#pragma unroll
    for (int i = 0; i < 20; i++) {
        v[i] = __expf(v[i] - m);
        l += v[i];
    }
#pragma unroll
    for (int o = 16; o; o >>= 1) l += __shfl_xor_sync(0xffffffffu, l, o);
    if (lane == 0) red[wid] = l;
    __syncthreads();
    float lt = 0.f;
#pragma unroll
    for (int w = 0; w < 8; w++) lt += red[w];
    float inv = 1.0f / lt;

    bf16* ph = Ph + row * KVLEN;
    bf16* pl = Pl + row * KVLEN;
#pragma unroll
    for (int i = 0; i < 20; i++) {
        float p = v[i] * inv;
        bf16 h, lo;
        split2(p, h, lo);
        ph[tid + i * 256] = h;
        pl[tid + i * 256] = lo;
    }
}

// ---------------------------------------------------------------------------
extern "C" void kernel_launch(void* const* d_in, const int* in_sizes, int n_in,
                              void* d_out, int out_size) {
    const float* X  = (const float*)d_in[0];
    const float* Wq = (const float*)d_in[1];
    const float* Wk = (const float*)d_in[2];
    const float* Wv = (const float*)d_in[3];
    const float* cK = (const float*)d_in[4];
    const float* cV = (const float*)d_in[5];
    float* out = (float*)d_out;

    float *Xn, *qkv;
    bf16 *Xhi, *Xlo, *Wthi, *Wtlo, *Qhi, *Qlo, *Khi, *Klo, *Vthi, *Vtlo, *Phi, *Plo;
    float* S;
    cudaGetSymbolAddress((void**)&Xn, g_Xn);
    cudaGetSymbolAddress((void**)&qkv, g_qkv);
    cudaGetSymbolAddress((void**)&Xhi, g_Xhi);
    cudaGetSymbolAddress((void**)&Xlo, g_Xlo);
    cudaGetSymbolAddress((void**)&Wthi, g_Wthi);
    cudaGetSymbolAddress((void**)&Wtlo, g_Wtlo);
    cudaGetSymbolAddress((void**)&Qhi, g_Qhi);
    cudaGetSymbolAddress((void**)&Qlo, g_Qlo);
    cudaGetSymbolAddress((void**)&Khi, g_Khi);
    cudaGetSymbolAddress((void**)&Klo, g_Klo);
    cudaGetSymbolAddress((void**)&Vthi, g_Vthi);
    cudaGetSymbolAddress((void**)&Vtlo, g_Vtlo);
    cudaGetSymbolAddress((void**)&S, g_S);
    cudaGetSymbolAddress((void**)&Phi, g_Phi);
    cudaGetSymbolAddress((void**)&Plo, g_Plo);

    float* q = qkv;
    float* k = qkv + (size_t)MN;
    float* v = qkv + 2ull * MN;

    const int SM256 = (128 + 128 + 256 + 256) * 80;   // 61440
    const int SM128 = (128 + 128 + 128 + 128) * 80;   // 40960
    cudaFuncSetAttribute(gemm3<256, 64>, cudaFuncAttributeMaxDynamicSharedMemorySize, SM256);
    cudaFuncSetAttribute(gemm3<128, 32>, cudaFuncAttributeMaxDynamicSharedMemorySize, SM128);

    // 1) RMSNorm X, split
    rmsnorm_x_kernel<<<MM, 256>>>(X, Xn);
    split_kernel<<<MN / 1024, 256>>>(Xn, Xhi, Xlo);

    // 2) W transpose+split
    dim3 wgrid(NN / 32, NN / 32);
    wsplit_kernel<<<wgrid, 256>>>(Wq, Wthi + 0ull * NN * NN, Wtlo + 0ull * NN * NN);
    wsplit_kernel<<<wgrid, 256>>>(Wk, Wthi + 1ull * NN * NN, Wtlo + 1ull * NN * NN);
    wsplit_kernel<<<wgrid, 256>>>(Wv, Wthi + 2ull * NN * NN, Wtlo + 2ull * NN * NN);

    // 3) QKV = Xn @ W  (batch 3)
    gemm3<256, 64><<<dim3(NN / 256, MM / 128, 3), 256, SM256>>>(
        Xhi, Xlo, Wthi, Wtlo, qkv, NN, NN, NN, NN,
        0LL, (long long)NN * NN, (long long)MN);

    // 4) qk-norm, split q
    qknorm_kernel<<<(2 * MM * HH * 32) / 256, 256>>>(q, k);
    split_kernel<<<MN / 1024, 256>>>(q, Qhi, Qlo);

    // 5) combined KV cache splits
    build_khl<<<(int)((size_t)HH * KVLEN * DD / 1024), 256>>>(cK, k, Khi, Klo);
    build_vt<<<dim3(KVLEN / 32, DD / 32, HH), 256>>>(cV, v, Vthi, Vtlo);

    // 6) logits S[h] = qn @ K[h]^T   (M=1024, N=5120, K=128, batch 32)
    gemm3<256, 64><<<dim3(KVLEN / 256, MM / 128, HH), 256, SM256>>>(
        Qhi, Qlo, Khi, Klo, S, DD, NN, DD, KVLEN,
        (long long)DD, (long long)KVLEN * DD, (long long)MM * KVLEN);

    // 7) softmax rows -> P hi/lo
    softmax_kernel<<<HH * MM, 256>>>(S, Phi, Plo);

    // 8) out[h] = P[h] @ V[h]   (M=1024, N=128, K=5120, batch 32) -> d_out
    gemm3<128, 32><<<dim3(DD / 128, MM / 128, HH), 256, SM128>>>(
        Phi, Plo, Vthi, Vtlo, out, KVLEN, KVLEN, KVLEN, NN,
        (long long)MM * KVLEN, (long long)DD * KVLEN, (long long)DD);
}

// round 6
// speedup vs baseline: 3.1683x; 1.1746x over previous
#include <cuda_runtime.h>
#include <cuda_bf16.h>
#include <math.h>
#include <stdint.h>

typedef __nv_bfloat16 bf16;

// Problem constants
#define MM 1024
#define NN 4096
#define DD 128
#define HH 32
#define PP 4096
#define KVLEN 5120   // PP + MM
#define MN (MM * NN)

// ---------------------------------------------------------------------------
// Scratch (allocation-free rule: __device__ globals)
// ---------------------------------------------------------------------------
__device__ float g_Xn[MN];
__device__ float g_qkv[3ull * MN];                   // q | k | v
__device__ bf16 g_Xhi[MN];
__device__ bf16 g_Xlo[MN];
__device__ bf16 g_Wthi[3ull * NN * NN];              // W transposed [n][k], hi
__device__ bf16 g_Wtlo[3ull * NN * NN];
__device__ bf16 g_Qhi[MN];
__device__ bf16 g_Qlo[MN];
__device__ bf16 g_Khi[(size_t)HH * KVLEN * DD];      // [h][kv][d]
__device__ bf16 g_Klo[(size_t)HH * KVLEN * DD];
__device__ bf16 g_Vthi[(size_t)HH * DD * KVLEN];     // [h][d][kv]
__device__ bf16 g_Vtlo[(size_t)HH * DD * KVLEN];
__device__ float g_S[(size_t)HH * MM * KVLEN];       // logits
__device__ bf16 g_Phi[(size_t)HH * MM * KVLEN];
__device__ bf16 g_Plo[(size_t)HH * MM * KVLEN];

// ---------------------------------------------------------------------------
// Helpers
// ---------------------------------------------------------------------------
__device__ __forceinline__ uint32_t smem_u32(const void* p) {
    uint32_t a;
    asm("{ .reg .u64 t; cvta.to.shared.u64 t, %1; cvt.u32.u64 %0, t; }" : "=r"(a) : "l"(p));
    return a;
}
__device__ __forceinline__ void ldsm_x4(uint32_t* r, uint32_t addr) {
    asm volatile("ldmatrix.sync.aligned.m8n8.x4.shared.b16 {%0,%1,%2,%3}, [%4];"
                 : "=r"(r[0]), "=r"(r[1]), "=r"(r[2]), "=r"(r[3]) : "r"(addr));
}
__device__ __forceinline__ void ldsm_x2(uint32_t* r, uint32_t addr) {
    asm volatile("ldmatrix.sync.aligned.m8n8.x2.shared.b16 {%0,%1}, [%2];"
                 : "=r"(r[0]), "=r"(r[1]) : "r"(addr));
}
__device__ __forceinline__ void cp16(uint32_t saddr, const void* gaddr) {
    asm volatile("cp.async.cg.shared.global [%0], [%1], 16;"
                 :: "r"(saddr), "l"(gaddr) : "memory");
}
#define CP_COMMIT() asm volatile("cp.async.commit_group;" ::: "memory")
#define CP_WAIT1() asm volatile("cp.async.wait_group 1;" ::: "memory")
#define CP_WAIT0() asm volatile("cp.async.wait_group 0;" ::: "memory")

#define MMA16816(d, a, b)                                              \
    asm volatile(                                                      \
        "mma.sync.aligned.m16n8k16.row.col.f32.bf16.bf16.f32 "         \
        "{%0,%1,%2,%3}, {%4,%5,%6,%7}, {%8,%9}, {%0,%1,%2,%3};"        \
        : "+f"((d)[0]), "+f"((d)[1]), "+f"((d)[2]), "+f"((d)[3])       \
        : "r"((a)[0]), "r"((a)[1]), "r"((a)[2]), "r"((a)[3]),          \
          "r"((b)[0]), "r"((b)[1]))

__device__ __forceinline__ void split2(float x, bf16& h, bf16& l) {
    h = __float2bfloat16(x);
    l = __float2bfloat16(x - __bfloat162float(h));
}

// ---------------------------------------------------------------------------
// RMSNorm over rows of X [1024, 4096]
// ---------------------------------------------------------------------------
__global__ __launch_bounds__(256) void rmsnorm_x_kernel(const float* __restrict__ X,
                                                        float* __restrict__ Y) {
    int row = blockIdx.x;
    const float4* x4 = (const float4*)(X + (size_t)row * NN);
    float4* y4 = (float4*)(Y + (size_t)row * NN);
    float4 v[4];
    float ss = 0.f;
#pragma unroll
    for (int i = 0; i < 4; i++) {
        v[i] = x4[threadIdx.x + i * 256];
        ss += v[i].x * v[i].x + v[i].y * v[i].y + v[i].z * v[i].z + v[i].w * v[i].w;
    }
#pragma unroll
    for (int o = 16; o; o >>= 1) ss += __shfl_xor_sync(0xffffffffu, ss, o);
    __shared__ float wsum[8];
    int warp = threadIdx.x >> 5, lane = threadIdx.x & 31;
    if (lane == 0) wsum[warp] = ss;
    __syncthreads();
    float tot = 0.f;
#pragma unroll
    for (int w = 0; w < 8; w++) tot += wsum[w];
    float s = rsqrtf(tot * (1.0f / (float)NN));
#pragma unroll
    for (int i = 0; i < 4; i++) {
        v[i].x *= s; v[i].y *= s; v[i].z *= s; v[i].w *= s;
        y4[threadIdx.x + i * 256] = v[i];
    }
}

// ---------------------------------------------------------------------------
// Generic fp32 -> bf16 hi/lo split (vectorized x4)
// ---------------------------------------------------------------------------
__global__ __launch_bounds__(256) void split_kernel(const float* __restrict__ src,
                                                    bf16* __restrict__ hi,
                                                    bf16* __restrict__ lo) {
    size_t i = ((size_t)blockIdx.x * 256 + threadIdx.x) * 4;
    float4 v = *(const float4*)(src + i);
    bf16 h0, h1, h2, h3, l0, l1, l2, l3;
    split2(v.x, h0, l0); split2(v.y, h1, l1);
    split2(v.z, h2, l2); split2(v.w, h3, l3);
    *(__nv_bfloat162*)(hi + i)     = __nv_bfloat162(h0, h1);
    *(__nv_bfloat162*)(hi + i + 2) = __nv_bfloat162(h2, h3);
    *(__nv_bfloat162*)(lo + i)     = __nv_bfloat162(l0, l1);
    *(__nv_bfloat162*)(lo + i + 2) = __nv_bfloat162(l2, l3);
}

// ---------------------------------------------------------------------------
// Transpose + split W [K, N] fp32 -> Wt hi/lo bf16 [N, K]
// ---------------------------------------------------------------------------
__global__ __launch_bounds__(256) void wsplit_kernel(const float* __restrict__ W,
                                                     bf16* __restrict__ hi,
                                                     bf16* __restrict__ lo) {
    __shared__ float t[32][33];
    int tx = threadIdx.x & 31, ty = threadIdx.x >> 5;
    int n0 = blockIdx.x * 32, k0 = blockIdx.y * 32;
#pragma unroll
    for (int i = 0; i < 4; i++)
        t[ty + i * 8][tx] = W[(size_t)(k0 + ty + i * 8) * NN + n0 + tx];
    __syncthreads();
#pragma unroll
    for (int i = 0; i < 4; i++) {
        float v = t[tx][ty + i * 8];
        bf16 h, l;
        split2(v, h, l);
        size_t off = (size_t)(n0 + ty + i * 8) * NN + k0 + tx;
        hi[off] = h;
        lo[off] = l;
    }
}

// ---------------------------------------------------------------------------
// Per-head RMSNorm over D=128.  q rows: norm + split -> Qh/Ql.
// k rows: norm in place (consumed by build_khl).
// ---------------------------------------------------------------------------
__global__ __launch_bounds__(256) void qknorm_split_kernel(const float* __restrict__ q,
                                                           float* __restrict__ k,
                                                           bf16* __restrict__ Qh,
                                                           bf16* __restrict__ Ql) {
    int gw = (int)((blockIdx.x * blockDim.x + threadIdx.x) >> 5);
    int lane = threadIdx.x & 31;
    bool isq = (gw < MM * HH);
    int row = isq ? gw : gw - MM * HH;
    const float* src = isq ? q : k;
    float4 a = ((const float4*)(src + (size_t)row * DD))[lane];
    float ss = a.x * a.x + a.y * a.y + a.z * a.z + a.w * a.w;
#pragma unroll
    for (int o = 16; o; o >>= 1) ss += __shfl_xor_sync(0xffffffffu, ss, o);
    float s = rsqrtf(ss * (1.0f / (float)DD));
    a.x *= s; a.y *= s; a.z *= s; a.w *= s;
    if (isq) {
        bf16 h0, h1, h2, h3, l0, l1, l2, l3;
        split2(a.x, h0, l0); split2(a.y, h1, l1);
        split2(a.z, h2, l2); split2(a.w, h3, l3);
        size_t off = (size_t)row * DD + lane * 4;
        *(__nv_bfloat162*)(Qh + off)     = __nv_bfloat162(h0, h1);
        *(__nv_bfloat162*)(Qh + off + 2) = __nv_bfloat162(h2, h3);
        *(__nv_bfloat162*)(Ql + off)     = __nv_bfloat162(l0, l1);
        *(__nv_bfloat162*)(Ql + off + 2) = __nv_bfloat162(l2, l3);
    } else {
        ((float4*)(k + (size_t)row * DD))[lane] = a;
    }
}

// ---------------------------------------------------------------------------
// Build K cache (combined) hi/lo: [h][kv][d], kv<PP from cache_K else k proj
// ---------------------------------------------------------------------------
__global__ __launch_bounds__(256) void build_khl(const float* __restrict__ cacheK,
                                                 const float* __restrict__ kproj,
                                                 bf16* __restrict__ Kh,
                                                 bf16* __restrict__ Kl) {
    size_t e = ((size_t)blockIdx.x * 256 + threadIdx.x) * 4;
    int h = (int)(e / ((size_t)KVLEN * DD));
    int rem = (int)(e % ((size_t)KVLEN * DD));
    int r = rem / DD, c = rem % DD;
    const float* src = (r < PP)
        ? cacheK + (((size_t)h * PP + r) * DD + c)
        : kproj + ((size_t)(r - PP) * NN + h * DD + c);
    float4 v = *(const float4*)src;
    bf16 h0, h1, h2, h3, l0, l1, l2, l3;
    split2(v.x, h0, l0); split2(v.y, h1, l1);
    split2(v.z, h2, l2); split2(v.w, h3, l3);
    *(__nv_bfloat162*)(Kh + e)     = __nv_bfloat162(h0, h1);
    *(__nv_bfloat162*)(Kh + e + 2) = __nv_bfloat162(h2, h3);
    *(__nv_bfloat162*)(Kl + e)     = __nv_bfloat162(l0, l1);
    *(__nv_bfloat162*)(Kl + e + 2) = __nv_bfloat162(l2, l3);
}

// ---------------------------------------------------------------------------
// Build V^T hi/lo: [h][d][kv] (transposed), sources cache_V and v proj
// ---------------------------------------------------------------------------
__global__ __launch_bounds__(256) void build_vt(const float* __restrict__ cacheV,
                                                const float* __restrict__ vproj,
                                                bf16* __restrict__ Vh,
                                                bf16* __restrict__ Vl) {
    __shared__ float t[32][33];
    int tx = threadIdx.x & 31, ty = threadIdx.x >> 5;
    int kv0 = blockIdx.x * 32, d0 = blockIdx.y * 32, h = blockIdx.z;
#pragma unroll
    for (int i = 0; i < 4; i++) {
        int r = kv0 + ty + i * 8;
        int c = d0 + tx;
        float v = (r < PP)
            ? cacheV[((size_t)h * PP + r) * DD + c]
            : vproj[(size_t)(r - PP) * NN + h * DD + c];
        t[ty + i * 8][tx] = v;
    }
    __syncthreads();
#pragma unroll
    for (int i = 0; i < 4; i++) {
        int d = d0 + ty + i * 8;
        float v = t[tx][ty + i * 8];
        bf16 hh, ll;
        split2(v, hh, ll);
        size_t off = ((size_t)h * DD + d) * KVLEN + kv0 + tx;
        Vh[off] = hh;
        Vl[off] = ll;
    }
}

// ---------------------------------------------------------------------------
// bf16x3 GEMM on tensor cores (mma.sync m16n8k16) + 2-stage cp.async pipeline.
// C[M,N] = A[M,K] @ B[N,K]^T,  C = Ah*Bh + Ah*Bl + Al*Bh.
// BM=128, 256 threads = 2x4 warps, warp tile 64 x WN.
// ---------------------------------------------------------------------------
template <int BN, int WN>
__global__ __launch_bounds__(256, 1) void gemm3(
    const bf16* __restrict__ Ah, const bf16* __restrict__ Al,
    const bf16* __restrict__ Bh, const bf16* __restrict__ Bl,
    float* __restrict__ C, int K, int lda, int ldb, int ldc,
    long long sA, long long sB, long long sC) {
    constexpr int BM = 128;
    constexpr int NFR = WN / 8;
    constexpr int PADB = 80;   // bytes per padded smem row (32 bf16 + 8 pad)
    constexpr int STG = (2 * BM + 2 * BN) * PADB;   // bytes per stage
    extern __shared__ char smraw[];

    const int tid = threadIdx.x;
    const int lane = tid & 31, wid = tid >> 5;
    const int wr = wid >> 2, wc = wid & 3;
    const int m0 = blockIdx.y * BM, n0 = blockIdx.x * BN;
    Ah += (long long)blockIdx.z * sA;
    Al += (long long)blockIdx.z * sA;
    Bh += (long long)blockIdx.z * sB;
    Bl += (long long)blockIdx.z * sB;
    C += (long long)blockIdx.z * sC;

    float acc[4][NFR][4];
#pragma unroll
    for (int f = 0; f < 4; f++)
#pragma unroll
        for (int j = 0; j < NFR; j++)
#pragma unroll
            for (int x = 0; x < 4; x++) acc[f][j][x] = 0.f;

    const uint32_t sbase = smem_u32(smraw);
    const uint32_t aoff = (uint32_t)((wr * 64 + (lane & 15)) * PADB + (lane >> 4) * 16);
    const uint32_t boff = (uint32_t)((wc * WN + (lane & 7)) * PADB + ((lane >> 3) & 1) * 16);

    // Issue cp.async fills for stage s covering K chunk starting at k0
    auto issue = [&](int s, int k0) {
        uint32_t ba = sbase + s * STG;
        const bf16* pAh = Ah + (size_t)m0 * lda + k0;
        const bf16* pAl = Al + (size_t)m0 * lda + k0;
#pragma unroll
        for (int i = tid; i < BM * 4; i += 256) {
            int r = i >> 2, cb = (i & 3) * 16;
            cp16(ba + r * PADB + cb, (const char*)(pAh + (size_t)r * lda) + cb);
            cp16(ba + BM * PADB + r * PADB + cb, (const char*)(pAl + (size_t)r * lda) + cb);
        }
        uint32_t bb = ba + 2 * BM * PADB;
        const bf16* pBh = Bh + (size_t)n0 * ldb + k0;
        const bf16* pBl = Bl + (size_t)n0 * ldb + k0;
#pragma unroll
        for (int i = tid; i < BN * 4; i += 256) {
            int r = i >> 2, cb = (i & 3) * 16;
            cp16(bb + r * PADB + cb, (const char*)(pBh + (size_t)r * ldb) + cb);
            cp16(bb + BN * PADB + r * PADB + cb, (const char*)(pBl + (size_t)r * ldb) + cb);
        }
        CP_COMMIT();
    };

    const int nch = K >> 5;
    issue(0, 0);

    for (int kc = 0; kc < nch; kc++) {
        const int s = kc & 1;
        if (kc + 1 < nch) {
            issue(s ^ 1, (kc + 1) << 5);
            CP_WAIT1();
        } else {
            CP_WAIT0();
        }
        __syncthreads();

        const uint32_t aH = sbase + s * STG;
        const uint32_t aL = aH + BM * PADB;
        const uint32_t bH = aL + BM * PADB;
        const uint32_t bL = bH + BN * PADB;
#pragma unroll
        for (int ks = 0; ks < 2; ks++) {
            uint32_t ah[4][4], al[4][4];
#pragma unroll
            for (int f = 0; f < 4; f++) {
                uint32_t off = aoff + f * 16 * PADB + ks * 32;
                ldsm_x4(ah[f], aH + off);
                ldsm_x4(al[f], aL + off);
            }
#pragma unroll
            for (int j = 0; j < NFR; j++) {
                uint32_t off = boff + j * 8 * PADB + ks * 32;
                uint32_t bh[2], bl[2];
                ldsm_x2(bh, bH + off);
                ldsm_x2(bl, bL + off);
#pragma unroll
                for (int f = 0; f < 4; f++) {
                    MMA16816(acc[f][j], ah[f], bh);
                    MMA16816(acc[f][j], ah[f], bl);
                    MMA16816(acc[f][j], al[f], bh);
                }
            }
        }
        __syncthreads();
    }

    // Epilogue
#pragma unroll
    for (int f = 0; f < 4; f++) {
        int row = m0 + wr * 64 + f * 16 + (lane >> 2);
#pragma unroll
        for (int j = 0; j < NFR; j++) {
            int col = n0 + wc * WN + j * 8 + (lane & 3) * 2;
            *(float2*)(C + (size_t)row * ldc + col) = make_float2(acc[f][j][0], acc[f][j][1]);
            *(float2*)(C + (size_t)(row + 8) * ldc + col) = make_float2(acc[f][j][2], acc[f][j][3]);
        }
    }
}

// ---------------------------------------------------------------------------
// Row softmax over KVLEN=5120, writes P = softmax(S) as hi/lo bf16
// ---------------------------------------------------------------------------
__global__ __launch_bounds__(256) void softmax_kernel(const float* __restrict__ S,
                                                      bf16* __restrict__ Ph,
                                                      bf16* __restrict__ Pl) {
    __shared__ float red[8];
    size_t row = blockIdx.x;
    const float* s = S + row * KVLEN;
    int tid = threadIdx.x, lane = tid & 31, wid = tid >> 5;
    float v[20];
    float mx = -INFINITY;
#pragma unroll
    for (int i = 0; i < 20; i++) {
        v[i] = s[tid + i * 256];
        mx = fmaxf(mx, v[i]);
    }
#pragma unroll
    for (int o = 16; o; o >>= 1) mx = fmaxf(mx, __shfl_xor_sync(0xffffffffu, mx, o));
    if (lane == 0) red[wid] = mx;
    __syncthreads();
    float m = -INFINITY;
#pragma unroll
    for (int w = 0; w < 8; w++) m = fmaxf(m, red[w]);
    __syncthreads();

    float l = 0.f;
#pragma unroll
    for (int i = 0; i < 20; i++) {
        v[i] = __expf(v[i] - m);
        l += v[i];
    }
#pragma unroll
    for (int o = 16; o; o >>= 1) l += __shfl_xor_sync(0xffffffffu, l, o);
    if (lane == 0) red[wid] = l;
    __syncthreads();
    float lt = 0.f;
#pragma unroll
    for (int w = 0; w < 8; w++) lt += red[w];
    float inv = 1.0f / lt;

    bf16* ph = Ph + row * KVLEN;
    bf16* pl = Pl + row * KVLEN;
#pragma unroll
    for (int i = 0; i < 20; i++) {
        float p = v[i] * inv;
        bf16 h, lo;
        split2(p, h, lo);
        ph[tid + i * 256] = h;
        pl[tid + i * 256] = lo;
    }
}

// ---------------------------------------------------------------------------
extern "C" void kernel_launch(void* const* d_in, const int* in_sizes, int n_in,
                              void* d_out, int out_size) {
    const float* X  = (const float*)d_in[0];
    const float* Wq = (const float*)d_in[1];
    const float* Wk = (const float*)d_in[2];
    const float* Wv = (const float*)d_in[3];
    const float* cK = (const float*)d_in[4];
    const float* cV = (const float*)d_in[5];
    float* out = (float*)d_out;

    float *Xn, *qkv;
    bf16 *Xhi, *Xlo, *Wthi, *Wtlo, *Qhi, *Qlo, *Khi, *Klo, *Vthi, *Vtlo, *Phi, *Plo;
    float* S;
    cudaGetSymbolAddress((void**)&Xn, g_Xn);
    cudaGetSymbolAddress((void**)&qkv, g_qkv);
    cudaGetSymbolAddress((void**)&Xhi, g_Xhi);
    cudaGetSymbolAddress((void**)&Xlo, g_Xlo);
    cudaGetSymbolAddress((void**)&Wthi, g_Wthi);
    cudaGetSymbolAddress((void**)&Wtlo, g_Wtlo);
    cudaGetSymbolAddress((void**)&Qhi, g_Qhi);
    cudaGetSymbolAddress((void**)&Qlo, g_Qlo);
    cudaGetSymbolAddress((void**)&Khi, g_Khi);
    cudaGetSymbolAddress((void**)&Klo, g_Klo);
    cudaGetSymbolAddress((void**)&Vthi, g_Vthi);
    cudaGetSymbolAddress((void**)&Vtlo, g_Vtlo);
    cudaGetSymbolAddress((void**)&S, g_S);
    cudaGetSymbolAddress((void**)&Phi, g_Phi);
    cudaGetSymbolAddress((void**)&Plo, g_Plo);

    float* q = qkv;
    float* k = qkv + (size_t)MN;
    float* v = qkv + 2ull * MN;

    const int SM256 = 2 * (2 * 128 + 2 * 256) * 80;   // 122880
    const int SM128 = 2 * (2 * 128 + 2 * 128) * 80;   // 81920
    cudaFuncSetAttribute(gemm3<256, 64>, cudaFuncAttributeMaxDynamicSharedMemorySize, SM256);
    cudaFuncSetAttribute(gemm3<128, 32>, cudaFuncAttributeMaxDynamicSharedMemorySize, SM128);

    // 1) RMSNorm X, split
    rmsnorm_x_kernel<<<MM, 256>>>(X, Xn);
    split_kernel<<<MN / 1024, 256>>>(Xn, Xhi, Xlo);

    // 2) W transpose+split
    dim3 wgrid(NN / 32, NN / 32);
    wsplit_kernel<<<wgrid, 256>>>(Wq, Wthi + 0ull * NN * NN, Wtlo + 0ull * NN * NN);
    wsplit_kernel<<<wgrid, 256>>>(Wk, Wthi + 1ull * NN * NN, Wtlo + 1ull * NN * NN);
    wsplit_kernel<<<wgrid, 256>>>(Wv, Wthi + 2ull * NN * NN, Wtlo + 2ull * NN * NN);

    // 3) QKV = Xn @ W  (batch 3)
    gemm3<256, 64><<<dim3(NN / 256, MM / 128, 3), 256, SM256>>>(
        Xhi, Xlo, Wthi, Wtlo, qkv, NN, NN, NN, NN,
        0LL, (long long)NN * NN, (long long)MN);

    // 4) qk-norm (q: norm+split to Qhi/Qlo; k: norm in place)
    qknorm_split_kernel<<<(2 * MM * HH * 32) / 256, 256>>>(q, k, Qhi, Qlo);

    // 5) combined KV cache splits
    build_khl<<<(int)((size_t)HH * KVLEN * DD / 1024), 256>>>(cK, k, Khi, Klo);
    build_vt<<<dim3(KVLEN / 32, DD / 32, HH), 256>>>(cV, v, Vthi, Vtlo);

    // 6) logits S[h] = qn @ K[h]^T   (M=1024, N=5120, K=128, batch 32)
    //    Q layout: element (m, d) of head h at m*NN + h*DD + d  ->  lda=NN, sA=DD
    gemm3<256, 64><<<dim3(KVLEN / 256, MM / 128, HH), 256, SM256>>>(
        Qhi, Qlo, Khi, Klo, S, DD, NN, DD, KVLEN,
        (long long)DD, (long long)KVLEN * DD, (long long)MM * KVLEN);

    // 7) softmax rows -> P hi/lo
    softmax_kernel<<<HH * MM, 256>>>(S, Phi, Plo);

    // 8) out[h] = P[h] @ V[h]   (M=1024, N=128, K=5120, batch 32) -> d_out
    gemm3<128, 32><<<dim3(DD / 128, MM / 128, HH), 256, SM128>>>(
        Phi, Plo, Vthi, Vtlo, out, KVLEN, KVLEN, KVLEN, NN,
        (long long)MM * KVLEN, (long long)DD * KVLEN, (long long)DD);
}

// round 7
// speedup vs baseline: 3.8251x; 1.2073x over previous
#include <cuda_runtime.h>
#include <cuda_bf16.h>
#include <math.h>
#include <stdint.h>

typedef __nv_bfloat16 bf16;

// Problem constants
#define MM 1024
#define NN 4096
#define DD 128
#define HH 32
#define PP 4096
#define KVLEN 5120   // PP + MM
#define MN (MM * NN)

// ---------------------------------------------------------------------------
// Scratch (allocation-free rule: __device__ globals)
// ---------------------------------------------------------------------------
__device__ float g_Xn[MN];
__device__ float g_qkv[3ull * MN];                   // q | k | v
__device__ bf16 g_Xhi[MN];
__device__ bf16 g_Xlo[MN];
__device__ bf16 g_Wthi[3ull * NN * NN];              // W transposed [n][k], hi
__device__ bf16 g_Wtlo[3ull * NN * NN];
__device__ bf16 g_Qhi[MN];
__device__ bf16 g_Qlo[MN];
__device__ bf16 g_Khi[(size_t)HH * KVLEN * DD];      // [h][kv][d]
__device__ bf16 g_Klo[(size_t)HH * KVLEN * DD];
__device__ bf16 g_Vthi[(size_t)HH * DD * KVLEN];     // [h][d][kv]
__device__ bf16 g_Vtlo[(size_t)HH * DD * KVLEN];

// ---------------------------------------------------------------------------
// Helpers
// ---------------------------------------------------------------------------
__device__ __forceinline__ uint32_t smem_u32(const void* p) {
    uint32_t a;
    asm("{ .reg .u64 t; cvta.to.shared.u64 t, %1; cvt.u32.u64 %0, t; }" : "=r"(a) : "l"(p));
    return a;
}
__device__ __forceinline__ void ldsm_x4(uint32_t* r, uint32_t addr) {
    asm volatile("ldmatrix.sync.aligned.m8n8.x4.shared.b16 {%0,%1,%2,%3}, [%4];"
                 : "=r"(r[0]), "=r"(r[1]), "=r"(r[2]), "=r"(r[3]) : "r"(addr));
}
__device__ __forceinline__ void ldsm_x2(uint32_t* r, uint32_t addr) {
    asm volatile("ldmatrix.sync.aligned.m8n8.x2.shared.b16 {%0,%1}, [%2];"
                 : "=r"(r[0]), "=r"(r[1]) : "r"(addr));
}
__device__ __forceinline__ void cp16(uint32_t saddr, const void* gaddr) {
    asm volatile("cp.async.cg.shared.global [%0], [%1], 16;"
                 :: "r"(saddr), "l"(gaddr) : "memory");
}
#define CP_COMMIT() asm volatile("cp.async.commit_group;" ::: "memory")
#define CP_WAIT1() asm volatile("cp.async.wait_group 1;" ::: "memory")
#define CP_WAIT0() asm volatile("cp.async.wait_group 0;" ::: "memory")

#define MMA16816(d, a, b)                                              \
    asm volatile(                                                      \
        "mma.sync.aligned.m16n8k16.row.col.f32.bf16.bf16.f32 "         \
        "{%0,%1,%2,%3}, {%4,%5,%6,%7}, {%8,%9}, {%0,%1,%2,%3};"        \
        : "+f"((d)[0]), "+f"((d)[1]), "+f"((d)[2]), "+f"((d)[3])       \
        : "r"((a)[0]), "r"((a)[1]), "r"((a)[2]), "r"((a)[3]),          \
          "r"((b)[0]), "r"((b)[1]))

__device__ __forceinline__ void split2(float x, bf16& h, bf16& l) {
    h = __float2bfloat16(x);
    l = __float2bfloat16(x - __bfloat162float(h));
}
__device__ __forceinline__ uint32_t packsplit_hi(float a, float b) {
    __nv_bfloat162 t(__float2bfloat16(a), __float2bfloat16(b));
    return *(uint32_t*)&t;
}
__device__ __forceinline__ uint32_t packsplit_lo(float a, float b) {
    bf16 ha = __float2bfloat16(a), hb = __float2bfloat16(b);
    __nv_bfloat162 t(__float2bfloat16(a - __bfloat162float(ha)),
                     __float2bfloat16(b - __bfloat162float(hb)));
    return *(uint32_t*)&t;
}

// ---------------------------------------------------------------------------
// RMSNorm over rows of X [1024, 4096]
// ---------------------------------------------------------------------------
__global__ __launch_bounds__(256) void rmsnorm_x_kernel(const float* __restrict__ X,
                                                        float* __restrict__ Y) {
    int row = blockIdx.x;
    const float4* x4 = (const float4*)(X + (size_t)row * NN);
    float4* y4 = (float4*)(Y + (size_t)row * NN);
    float4 v[4];
    float ss = 0.f;
#pragma unroll
    for (int i = 0; i < 4; i++) {
        v[i] = x4[threadIdx.x + i * 256];
        ss += v[i].x * v[i].x + v[i].y * v[i].y + v[i].z * v[i].z + v[i].w * v[i].w;
    }
#pragma unroll
    for (int o = 16; o; o >>= 1) ss += __shfl_xor_sync(0xffffffffu, ss, o);
    __shared__ float wsum[8];
    int warp = threadIdx.x >> 5, lane = threadIdx.x & 31;
    if (lane == 0) wsum[warp] = ss;
    __syncthreads();
    float tot = 0.f;
#pragma unroll
    for (int w = 0; w < 8; w++) tot += wsum[w];
    float s = rsqrtf(tot * (1.0f / (float)NN));
#pragma unroll
    for (int i = 0; i < 4; i++) {
        v[i].x *= s; v[i].y *= s; v[i].z *= s; v[i].w *= s;
        y4[threadIdx.x + i * 256] = v[i];
    }
}

// ---------------------------------------------------------------------------
// Generic fp32 -> bf16 hi/lo split (vectorized x4)
// ---------------------------------------------------------------------------
__global__ __launch_bounds__(256) void split_kernel(const float* __restrict__ src,
                                                    bf16* __restrict__ hi,
                                                    bf16* __restrict__ lo) {
    size_t i = ((size_t)blockIdx.x * 256 + threadIdx.x) * 4;
    float4 v = *(const float4*)(src + i);
    bf16 h0, h1, h2, h3, l0, l1, l2, l3;
    split2(v.x, h0, l0); split2(v.y, h1, l1);
    split2(v.z, h2, l2); split2(v.w, h3, l3);
    *(__nv_bfloat162*)(hi + i)     = __nv_bfloat162(h0, h1);
    *(__nv_bfloat162*)(hi + i + 2) = __nv_bfloat162(h2, h3);
    *(__nv_bfloat162*)(lo + i)     = __nv_bfloat162(l0, l1);
    *(__nv_bfloat162*)(lo + i + 2) = __nv_bfloat162(l2, l3);
}

// ---------------------------------------------------------------------------
// Transpose + split W [K, N] fp32 -> Wt hi/lo bf16 [N, K]
// ---------------------------------------------------------------------------
__global__ __launch_bounds__(256) void wsplit_kernel(const float* __restrict__ W,
                                                     bf16* __restrict__ hi,
                                                     bf16* __restrict__ lo) {
    __shared__ float t[32][33];
    int tx = threadIdx.x & 31, ty = threadIdx.x >> 5;
    int n0 = blockIdx.x * 32, k0 = blockIdx.y * 32;
#pragma unroll
    for (int i = 0; i < 4; i++)
        t[ty + i * 8][tx] = W[(size_t)(k0 + ty + i * 8) * NN + n0 + tx];
    __syncthreads();
#pragma unroll
    for (int i = 0; i < 4; i++) {
        float v = t[tx][ty + i * 8];
        bf16 h, l;
        split2(v, h, l);
        size_t off = (size_t)(n0 + ty + i * 8) * NN + k0 + tx;
        hi[off] = h;
        lo[off] = l;
    }
}

// ---------------------------------------------------------------------------
// Per-head RMSNorm over D=128.  q rows: norm + split -> Qh/Ql.
// k rows: norm in place (consumed by build_khl).
// ---------------------------------------------------------------------------
__global__ __launch_bounds__(256) void qknorm_split_kernel(const float* __restrict__ q,
                                                           float* __restrict__ k,
                                                           bf16* __restrict__ Qh,
                                                           bf16* __restrict__ Ql) {
    int gw = (int)((blockIdx.x * blockDim.x + threadIdx.x) >> 5);
    int lane = threadIdx.x & 31;
    bool isq = (gw < MM * HH);
    int row = isq ? gw : gw - MM * HH;
    const float* src = isq ? q : k;
    float4 a = ((const float4*)(src + (size_t)row * DD))[lane];
    float ss = a.x * a.x + a.y * a.y + a.z * a.z + a.w * a.w;
#pragma unroll
    for (int o = 16; o; o >>= 1) ss += __shfl_xor_sync(0xffffffffu, ss, o);
    float s = rsqrtf(ss * (1.0f / (float)DD));
    a.x *= s; a.y *= s; a.z *= s; a.w *= s;
    if (isq) {
        bf16 h0, h1, h2, h3, l0, l1, l2, l3;
        split2(a.x, h0, l0); split2(a.y, h1, l1);
        split2(a.z, h2, l2); split2(a.w, h3, l3);
        size_t off = (size_t)row * DD + lane * 4;
        *(__nv_bfloat162*)(Qh + off)     = __nv_bfloat162(h0, h1);
        *(__nv_bfloat162*)(Qh + off + 2) = __nv_bfloat162(h2, h3);
        *(__nv_bfloat162*)(Ql + off)     = __nv_bfloat162(l0, l1);
        *(__nv_bfloat162*)(Ql + off + 2) = __nv_bfloat162(l2, l3);
    } else {
        ((float4*)(k + (size_t)row * DD))[lane] = a;
    }
}

// ---------------------------------------------------------------------------
// Build K cache (combined) hi/lo: [h][kv][d]
// ---------------------------------------------------------------------------
__global__ __launch_bounds__(256) void build_khl(const float* __restrict__ cacheK,
                                                 const float* __restrict__ kproj,
                                                 bf16* __restrict__ Kh,
                                                 bf16* __restrict__ Kl) {
    size_t e = ((size_t)blockIdx.x * 256 + threadIdx.x) * 4;
    int h = (int)(e / ((size_t)KVLEN * DD));
    int rem = (int)(e % ((size_t)KVLEN * DD));
    int r = rem / DD, c = rem % DD;
    const float* src = (r < PP)
        ? cacheK + (((size_t)h * PP + r) * DD + c)
        : kproj + ((size_t)(r - PP) * NN + h * DD + c);
    float4 v = *(const float4*)src;
    bf16 h0, h1, h2, h3, l0, l1, l2, l3;
    split2(v.x, h0, l0); split2(v.y, h1, l1);
    split2(v.z, h2, l2); split2(v.w, h3, l3);
    *(__nv_bfloat162*)(Kh + e)     = __nv_bfloat162(h0, h1);
    *(__nv_bfloat162*)(Kh + e + 2) = __nv_bfloat162(h2, h3);
    *(__nv_bfloat162*)(Kl + e)     = __nv_bfloat162(l0, l1);
    *(__nv_bfloat162*)(Kl + e + 2) = __nv_bfloat162(l2, l3);
}

// ---------------------------------------------------------------------------
// Build V^T hi/lo: [h][d][kv]
// ---------------------------------------------------------------------------
__global__ __launch_bounds__(256) void build_vt(const float* __restrict__ cacheV,
                                                const float* __restrict__ vproj,
                                                bf16* __restrict__ Vh,
                                                bf16* __restrict__ Vl) {
    __shared__ float t[32][33];
    int tx = threadIdx.x & 31, ty = threadIdx.x >> 5;
    int kv0 = blockIdx.x * 32, d0 = blockIdx.y * 32, h = blockIdx.z;
#pragma unroll
    for (int i = 0; i < 4; i++) {
        int r = kv0 + ty + i * 8;
        int c = d0 + tx;
        float v = (r < PP)
            ? cacheV[((size_t)h * PP + r) * DD + c]
            : vproj[(size_t)(r - PP) * NN + h * DD + c];
        t[ty + i * 8][tx] = v;
    }
    __syncthreads();
#pragma unroll
    for (int i = 0; i < 4; i++) {
        int d = d0 + ty + i * 8;
        float v = t[tx][ty + i * 8];
        bf16 hh, ll;
        split2(v, hh, ll);
        size_t off = ((size_t)h * DD + d) * KVLEN + kv0 + tx;
        Vh[off] = hh;
        Vl[off] = ll;
    }
}

// ---------------------------------------------------------------------------
// bf16x3 GEMM (mma.sync m16n8k16) + 2-stage cp.async pipeline (QKV proj).
// ---------------------------------------------------------------------------
template <int BN, int WN>
__global__ __launch_bounds__(256, 1) void gemm3(
    const bf16* __restrict__ Ah, const bf16* __restrict__ Al,
    const bf16* __restrict__ Bh, const bf16* __restrict__ Bl,
    float* __restrict__ C, int K, int lda, int ldb, int ldc,
    long long sA, long long sB, long long sC) {
    constexpr int BM = 128;
    constexpr int NFR = WN / 8;
    constexpr int PADB = 80;
    constexpr int STG = (2 * BM + 2 * BN) * PADB;
    extern __shared__ char smraw[];

    const int tid = threadIdx.x;
    const int lane = tid & 31, wid = tid >> 5;
    const int wr = wid >> 2, wc = wid & 3;
    const int m0 = blockIdx.y * BM, n0 = blockIdx.x * BN;
    Ah += (long long)blockIdx.z * sA;
    Al += (long long)blockIdx.z * sA;
    Bh += (long long)blockIdx.z * sB;
    Bl += (long long)blockIdx.z * sB;
    C += (long long)blockIdx.z * sC;

    float acc[4][NFR][4];
#pragma unroll
    for (int f = 0; f < 4; f++)
#pragma unroll
        for (int j = 0; j < NFR; j++)
#pragma unroll
            for (int x = 0; x < 4; x++) acc[f][j][x] = 0.f;

    const uint32_t sbase = smem_u32(smraw);
    const uint32_t aoff = (uint32_t)((wr * 64 + (lane & 15)) * PADB + (lane >> 4) * 16);
    const uint32_t boff = (uint32_t)((wc * WN + (lane & 7)) * PADB + ((lane >> 3) & 1) * 16);

    auto issue = [&](int s, int k0) {
        uint32_t ba = sbase + s * STG;
        const bf16* pAh = Ah + (size_t)m0 * lda + k0;
        const bf16* pAl = Al + (size_t)m0 * lda + k0;
#pragma unroll
        for (int i = tid; i < BM * 4; i += 256) {
            int r = i >> 2, cb = (i & 3) * 16;
            cp16(ba + r * PADB + cb, (const char*)(pAh + (size_t)r * lda) + cb);
            cp16(ba + BM * PADB + r * PADB + cb, (const char*)(pAl + (size_t)r * lda) + cb);
        }
        uint32_t bb = ba + 2 * BM * PADB;
        const bf16* pBh = Bh + (size_t)n0 * ldb + k0;
        const bf16* pBl = Bl + (size_t)n0 * ldb + k0;
#pragma unroll
        for (int i = tid; i < BN * 4; i += 256) {
            int r = i >> 2, cb = (i & 3) * 16;
            cp16(bb + r * PADB + cb, (const char*)(pBh + (size_t)r * ldb) + cb);
            cp16(bb + BN * PADB + r * PADB + cb, (const char*)(pBl + (size_t)r * ldb) + cb);
        }
        CP_COMMIT();
    };

    const int nch = K >> 5;
    issue(0, 0);

    for (int kc = 0; kc < nch; kc++) {
        const int s = kc & 1;
        if (kc + 1 < nch) {
            issue(s ^ 1, (kc + 1) << 5);
            CP_WAIT1();
        } else {
            CP_WAIT0();
        }
        __syncthreads();

        const uint32_t aH = sbase + s * STG;
        const uint32_t aL = aH + BM * PADB;
        const uint32_t bH = aL + BM * PADB;
        const uint32_t bL = bH + BN * PADB;
#pragma unroll
        for (int ks = 0; ks < 2; ks++) {
            uint32_t ah[4][4], al[4][4];
#pragma unroll
            for (int f = 0; f < 4; f++) {
                uint32_t off = aoff + f * 16 * PADB + ks * 32;
                ldsm_x4(ah[f], aH + off);
                ldsm_x4(al[f], aL + off);
            }
#pragma unroll
            for (int j = 0; j < NFR; j++) {
                uint32_t off = boff + j * 8 * PADB + ks * 32;
                uint32_t bh[2], bl[2];
                ldsm_x2(bh, bH + off);
                ldsm_x2(bl, bL + off);
#pragma unroll
                for (int f = 0; f < 4; f++) {
                    MMA16816(acc[f][j], ah[f], bh);
                    MMA16816(acc[f][j], ah[f], bl);
                    MMA16816(acc[f][j], al[f], bh);
                }
            }
        }
        __syncthreads();
    }

#pragma unroll
    for (int f = 0; f < 4; f++) {
        int row = m0 + wr * 64 + f * 16 + (lane >> 2);
#pragma unroll
        for (int j = 0; j < NFR; j++) {
            int col = n0 + wc * WN + j * 8 + (lane & 3) * 2;
            *(float2*)(C + (size_t)row * ldc + col) = make_float2(acc[f][j][0], acc[f][j][1]);
            *(float2*)(C + (size_t)(row + 8) * ldc + col) = make_float2(acc[f][j][2], acc[f][j][3]);
        }
    }
}

// ---------------------------------------------------------------------------
// Fused flash attention on mma.sync, bf16x3 for QK^T and PV.
// Block: 128 q-rows x 1 head. 8 warps, each owns 16 rows.
// KV chunks of 64, 2-stage cp.async. Online softmax in registers.
// Smem: Qh/Ql [128][272B], per stage: Kh/Kl [64][272B] + Vh/Vl [128][144B].
// ---------------------------------------------------------------------------
#define FA_KPAD 272
#define FA_VPAD 144
#define FA_QB (128 * FA_KPAD)              // 34816
#define FA_KT (64 * FA_KPAD)               // 17408
#define FA_VT (128 * FA_VPAD)              // 18432
#define FA_STG (2 * FA_KT + 2 * FA_VT)     // 71680
#define FA_SMEM (2 * FA_QB + 2 * FA_STG)   // 212992

__global__ __launch_bounds__(256, 1) void attn_fused(
    const bf16* __restrict__ Qh_, const bf16* __restrict__ Ql_,
    const bf16* __restrict__ Kh_, const bf16* __restrict__ Kl_,
    const bf16* __restrict__ Vh_, const bf16* __restrict__ Vl_,
    float* __restrict__ out) {
    extern __shared__ char sm[];
    const int tid = threadIdx.x, lane = tid & 31, wid = tid >> 5;
    const int m0 = blockIdx.x * 128, h = blockIdx.y;
    const uint32_t sb = smem_u32(sm);

    // Load Q tile (hi/lo) into smem: 128 rows x 256B each
#pragma unroll
    for (int i = tid; i < 128 * 16; i += 256) {
        int r = i >> 4, c = i & 15;
        size_t go = (size_t)(m0 + r) * NN + h * DD + c * 8;
        *(float4*)(sm + r * FA_KPAD + c * 16) = *(const float4*)(Qh_ + go);
        *(float4*)(sm + FA_QB + r * FA_KPAD + c * 16) = *(const float4*)(Ql_ + go);
    }

    const bf16* Khh = Kh_ + (size_t)h * KVLEN * DD;
    const bf16* Klh = Kl_ + (size_t)h * KVLEN * DD;
    const bf16* Vhh = Vh_ + (size_t)h * DD * KVLEN;
    const bf16* Vlh = Vl_ + (size_t)h * DD * KVLEN;

    auto issue = [&](int s, int kv0) {
        uint32_t kb = sb + 2 * FA_QB + s * FA_STG;
#pragma unroll
        for (int i = tid; i < 1024; i += 256) {
            int r = i >> 4, c = i & 15;
            size_t go = (size_t)(kv0 + r) * DD + c * 8;
            cp16(kb + r * FA_KPAD + c * 16, Khh + go);
            cp16(kb + FA_KT + r * FA_KPAD + c * 16, Klh + go);
        }
        uint32_t vb = kb + 2 * FA_KT;
#pragma unroll
        for (int i = tid; i < 1024; i += 256) {
            int r = i >> 3, c = i & 7;
            size_t go = (size_t)r * KVLEN + kv0 + c * 8;
            cp16(vb + r * FA_VPAD + c * 16, Vhh + go);
            cp16(vb + FA_VT + r * FA_VPAD + c * 16, Vlh + go);
        }
        CP_COMMIT();
    };

    float oacc[16][4];
#pragma unroll
    for (int j = 0; j < 16; j++)
#pragma unroll
        for (int x = 0; x < 4; x++) oacc[j][x] = 0.f;
    float mrow0 = -INFINITY, mrow8 = -INFINITY;
    float lrow0 = 0.f, lrow8 = 0.f;

    const uint32_t qoff = (uint32_t)((wid * 16 + (lane & 15)) * FA_KPAD + (lane >> 4) * 16);
    const uint32_t koff = (uint32_t)((lane & 7) * FA_KPAD + ((lane >> 3) & 1) * 16);
    const uint32_t voff = (uint32_t)((lane & 7) * FA_VPAD + ((lane >> 3) & 1) * 16);

    issue(0, 0);

    for (int ch = 0; ch < KVLEN / 64; ch++) {
        const int s = ch & 1;
        if (ch + 1 < KVLEN / 64) {
            issue(s ^ 1, (ch + 1) * 64);
            CP_WAIT1();
        } else {
            CP_WAIT0();
        }
        __syncthreads();

        const uint32_t bKh = sb + 2 * FA_QB + s * FA_STG;
        const uint32_t bKl = bKh + FA_KT;
        const uint32_t bVh = bKh + 2 * FA_KT;
        const uint32_t bVl = bVh + FA_VT;

        // S = Q @ K^T for this chunk: 8 j-tiles of 8 kv each
        float sacc[8][4];
#pragma unroll
        for (int j = 0; j < 8; j++)
#pragma unroll
            for (int x = 0; x < 4; x++) sacc[j][x] = 0.f;
#pragma unroll
        for (int ks = 0; ks < 8; ks++) {
            uint32_t qh[4], ql[4];
            ldsm_x4(qh, sb + qoff + ks * 32);
            ldsm_x4(ql, sb + FA_QB + qoff + ks * 32);
#pragma unroll
            for (int j = 0; j < 8; j++) {
                uint32_t kh[2], kl[2];
                uint32_t off = koff + j * 8 * FA_KPAD + ks * 32;
                ldsm_x2(kh, bKh + off);
                ldsm_x2(kl, bKl + off);
                MMA16816(sacc[j], qh, kh);
                MMA16816(sacc[j], qh, kl);
                MMA16816(sacc[j], ql, kh);
            }
        }

        // Online softmax (rows r = lane>>2 and r+8)
        float mx0 = -INFINITY, mx8 = -INFINITY;
#pragma unroll
        for (int j = 0; j < 8; j++) {
            mx0 = fmaxf(mx0, fmaxf(sacc[j][0], sacc[j][1]));
            mx8 = fmaxf(mx8, fmaxf(sacc[j][2], sacc[j][3]));
        }
        mx0 = fmaxf(mx0, __shfl_xor_sync(0xffffffffu, mx0, 1));
        mx0 = fmaxf(mx0, __shfl_xor_sync(0xffffffffu, mx0, 2));
        mx8 = fmaxf(mx8, __shfl_xor_sync(0xffffffffu, mx8, 1));
        mx8 = fmaxf(mx8, __shfl_xor_sync(0xffffffffu, mx8, 2));
        float mn0 = fmaxf(mrow0, mx0), mn8 = fmaxf(mrow8, mx8);
        float sc0 = __expf(mrow0 - mn0), sc8 = __expf(mrow8 - mn8);
        mrow0 = mn0; mrow8 = mn8;
        float ps0 = 0.f, ps8 = 0.f;
#pragma unroll
        for (int j = 0; j < 8; j++) {
            sacc[j][0] = __expf(sacc[j][0] - mn0);
            sacc[j][1] = __expf(sacc[j][1] - mn0);
            sacc[j][2] = __expf(sacc[j][2] - mn8);
            sacc[j][3] = __expf(sacc[j][3] - mn8);
            ps0 += sacc[j][0] + sacc[j][1];
            ps8 += sacc[j][2] + sacc[j][3];
        }
        lrow0 = lrow0 * sc0 + ps0;
        lrow8 = lrow8 * sc8 + ps8;
#pragma unroll
        for (int j = 0; j < 16; j++) {
            oacc[j][0] *= sc0; oacc[j][1] *= sc0;
            oacc[j][2] *= sc8; oacc[j][3] *= sc8;
        }

        // P fragments (A-frag of m16n8k16 over k=kv): hi/lo split in regs
        uint32_t ph[4][4], pl[4][4];
#pragma unroll
        for (int kk = 0; kk < 4; kk++) {
            ph[kk][0] = packsplit_hi(sacc[2 * kk][0], sacc[2 * kk][1]);
            ph[kk][1] = packsplit_hi(sacc[2 * kk][2], sacc[2 * kk][3]);
            ph[kk][2] = packsplit_hi(sacc[2 * kk + 1][0], sacc[2 * kk + 1][1]);
            ph[kk][3] = packsplit_hi(sacc[2 * kk + 1][2], sacc[2 * kk + 1][3]);
            pl[kk][0] = packsplit_lo(sacc[2 * kk][0], sacc[2 * kk][1]);
            pl[kk][1] = packsplit_lo(sacc[2 * kk][2], sacc[2 * kk][3]);
            pl[kk][2] = packsplit_lo(sacc[2 * kk + 1][0], sacc[2 * kk + 1][1]);
            pl[kk][3] = packsplit_lo(sacc[2 * kk + 1][2], sacc[2 * kk + 1][3]);
        }

        // O += P @ V^T : 16 output d-tiles of 8, k = 64 kv (4 steps)
#pragma unroll
        for (int kk = 0; kk < 4; kk++) {
#pragma unroll
            for (int j = 0; j < 16; j++) {
                uint32_t vh[2], vl[2];
                uint32_t off = voff + j * 8 * FA_VPAD + kk * 32;
                ldsm_x2(vh, bVh + off);
                ldsm_x2(vl, bVl + off);
                MMA16816(oacc[j], ph[kk], vh);
                MMA16816(oacc[j], ph[kk], vl);
                MMA16816(oacc[j], pl[kk], vh);
            }
        }
        __syncthreads();
    }

    // Finalize: full row sums, divide, write
    lrow0 += __shfl_xor_sync(0xffffffffu, lrow0, 1);
    lrow0 += __shfl_xor_sync(0xffffffffu, lrow0, 2);
    lrow8 += __shfl_xor_sync(0xffffffffu, lrow8, 1);
    lrow8 += __shfl_xor_sync(0xffffffffu, lrow8, 2);
    float inv0 = 1.0f / lrow0, inv8 = 1.0f / lrow8;
    int r0 = m0 + wid * 16 + (lane >> 2);
#pragma unroll
    for (int j = 0; j < 16; j++) {
        int col = h * DD + j * 8 + (lane & 3) * 2;
        *(float2*)(out + (size_t)r0 * NN + col) =
            make_float2(oacc[j][0] * inv0, oacc[j][1] * inv0);
        *(float2*)(out + (size_t)(r0 + 8) * NN + col) =
            make_float2(oacc[j][2] * inv8, oacc[j][3] * inv8);
    }
}

// ---------------------------------------------------------------------------
extern "C" void kernel_launch(void* const* d_in, const int* in_sizes, int n_in,
                              void* d_out, int out_size) {
    const float* X  = (const float*)d_in[0];
    const float* Wq = (const float*)d_in[1];
    const float* Wk = (const float*)d_in[2];
    const float* Wv = (const float*)d_in[3];
    const float* cK = (const float*)d_in[4];
    const float* cV = (const float*)d_in[5];
    float* out = (float*)d_out;

    float *Xn, *qkv;
    bf16 *Xhi, *Xlo, *Wthi, *Wtlo, *Qhi, *Qlo, *Khi, *Klo, *Vthi, *Vtlo;
    cudaGetSymbolAddress((void**)&Xn, g_Xn);
    cudaGetSymbolAddress((void**)&qkv, g_qkv);
    cudaGetSymbolAddress((void**)&Xhi, g_Xhi);
    cudaGetSymbolAddress((void**)&Xlo, g_Xlo);
    cudaGetSymbolAddress((void**)&Wthi, g_Wthi);
    cudaGetSymbolAddress((void**)&Wtlo, g_Wtlo);
    cudaGetSymbolAddress((void**)&Qhi, g_Qhi);
    cudaGetSymbolAddress((void**)&Qlo, g_Qlo);
    cudaGetSymbolAddress((void**)&Khi, g_Khi);
    cudaGetSymbolAddress((void**)&Klo, g_Klo);
    cudaGetSymbolAddress((void**)&Vthi, g_Vthi);
    cudaGetSymbolAddress((void**)&Vtlo, g_Vtlo);

    float* q = qkv;
    float* k = qkv + (size_t)MN;
    float* v = qkv + 2ull * MN;

    const int SM256 = 2 * (2 * 128 + 2 * 256) * 80;   // 122880
    cudaFuncSetAttribute(gemm3<256, 64>, cudaFuncAttributeMaxDynamicSharedMemorySize, SM256);
    cudaFuncSetAttribute(attn_fused, cudaFuncAttributeMaxDynamicSharedMemorySize, FA_SMEM);

    // 1) RMSNorm X, split
    rmsnorm_x_kernel<<<MM, 256>>>(X, Xn);
    split_kernel<<<MN / 1024, 256>>>(Xn, Xhi, Xlo);

    // 2) W transpose+split
    dim3 wgrid(NN / 32, NN / 32);
    wsplit_kernel<<<wgrid, 256>>>(Wq, Wthi + 0ull * NN * NN, Wtlo + 0ull * NN * NN);
    wsplit_kernel<<<wgrid, 256>>>(Wk, Wthi + 1ull * NN * NN, Wtlo + 1ull * NN * NN);
    wsplit_kernel<<<wgrid, 256>>>(Wv, Wthi + 2ull * NN * NN, Wtlo + 2ull * NN * NN);

    // 3) QKV = Xn @ W  (batch 3)
    gemm3<256, 64><<<dim3(NN / 256, MM / 128, 3), 256, SM256>>>(
        Xhi, Xlo, Wthi, Wtlo, qkv, NN, NN, NN, NN,
        0LL, (long long)NN * NN, (long long)MN);

    // 4) qk-norm (q: norm+split to Qhi/Qlo; k: norm in place)
    qknorm_split_kernel<<<(2 * MM * HH * 32) / 256, 256>>>(q, k, Qhi, Qlo);

    // 5) combined KV cache splits
    build_khl<<<(int)((size_t)HH * KVLEN * DD / 1024), 256>>>(cK, k, Khi, Klo);
    build_vt<<<dim3(KVLEN / 32, DD / 32, HH), 256>>>(cV, v, Vthi, Vtlo);

    // 6) fused flash attention -> d_out
    attn_fused<<<dim3(MM / 128, HH), 256, FA_SMEM>>>(
        Qhi, Qlo, Khi, Klo, Vthi, Vtlo, out);
}

// round 8
// speedup vs baseline: 3.9111x; 1.0225x over previous
#include <cuda_runtime.h>
#include <cuda_bf16.h>
#include <math.h>
#include <stdint.h>

typedef __nv_bfloat16 bf16;

// Problem constants
#define MM 1024
#define NN 4096
#define DD 128
#define HH 32
#define PP 4096
#define KVLEN 5120   // PP + MM
#define MN (MM * NN)

// ---------------------------------------------------------------------------
// Scratch (allocation-free rule: __device__ globals)
// ---------------------------------------------------------------------------
__device__ float g_qkv[3ull * MN];                   // q | k | v
__device__ bf16 g_Xhi[MN];
__device__ bf16 g_Xlo[MN];
__device__ bf16 g_Wthi[3ull * NN * NN];              // W transposed [n][k], hi
__device__ bf16 g_Wtlo[3ull * NN * NN];
__device__ bf16 g_Qhi[MN];
__device__ bf16 g_Qlo[MN];
__device__ bf16 g_Khi[(size_t)HH * KVLEN * DD];      // [h][kv][d]
__device__ bf16 g_Klo[(size_t)HH * KVLEN * DD];
__device__ bf16 g_Vthi[(size_t)HH * DD * KVLEN];     // [h][d][kv]
__device__ bf16 g_Vtlo[(size_t)HH * DD * KVLEN];

// ---------------------------------------------------------------------------
// Helpers
// ---------------------------------------------------------------------------
__device__ __forceinline__ uint32_t smem_u32(const void* p) {
    uint32_t a;
    asm("{ .reg .u64 t; cvta.to.shared.u64 t, %1; cvt.u32.u64 %0, t; }" : "=r"(a) : "l"(p));
    return a;
}
__device__ __forceinline__ void ldsm_x4(uint32_t* r, uint32_t addr) {
    asm volatile("ldmatrix.sync.aligned.m8n8.x4.shared.b16 {%0,%1,%2,%3}, [%4];"
                 : "=r"(r[0]), "=r"(r[1]), "=r"(r[2]), "=r"(r[3]) : "r"(addr));
}
__device__ __forceinline__ void ldsm_x2(uint32_t* r, uint32_t addr) {
    asm volatile("ldmatrix.sync.aligned.m8n8.x2.shared.b16 {%0,%1}, [%2];"
                 : "=r"(r[0]), "=r"(r[1]) : "r"(addr));
}
__device__ __forceinline__ void cp16(uint32_t saddr, const void* gaddr) {
    asm volatile("cp.async.cg.shared.global [%0], [%1], 16;"
                 :: "r"(saddr), "l"(gaddr) : "memory");
}
#define CP_COMMIT() asm volatile("cp.async.commit_group;" ::: "memory")
#define CP_WAIT1() asm volatile("cp.async.wait_group 1;" ::: "memory")
#define CP_WAIT0() asm volatile("cp.async.wait_group 0;" ::: "memory")

#define MMA16816(d, a, b)                                              \
    asm volatile(                                                      \
        "mma.sync.aligned.m16n8k16.row.col.f32.bf16.bf16.f32 "         \
        "{%0,%1,%2,%3}, {%4,%5,%6,%7}, {%8,%9}, {%0,%1,%2,%3};"        \
        : "+f"((d)[0]), "+f"((d)[1]), "+f"((d)[2]), "+f"((d)[3])       \
        : "r"((a)[0]), "r"((a)[1]), "r"((a)[2]), "r"((a)[3]),          \
          "r"((b)[0]), "r"((b)[1]))

__device__ __forceinline__ void split2(float x, bf16& h, bf16& l) {
    h = __float2bfloat16(x);
    l = __float2bfloat16(x - __bfloat162float(h));
}
__device__ __forceinline__ uint32_t packsplit_hi(float a, float b) {
    __nv_bfloat162 t(__float2bfloat16(a), __float2bfloat16(b));
    return *(uint32_t*)&t;
}
__device__ __forceinline__ uint32_t packsplit_lo(float a, float b) {
    bf16 ha = __float2bfloat16(a), hb = __float2bfloat16(b);
    __nv_bfloat162 t(__float2bfloat16(a - __bfloat162float(ha)),
                     __float2bfloat16(b - __bfloat162float(hb)));
    return *(uint32_t*)&t;
}

// ---------------------------------------------------------------------------
// RMSNorm over rows of X [1024, 4096], fused bf16 hi/lo split output
// ---------------------------------------------------------------------------
__global__ __launch_bounds__(256) void rmsnorm_split_x(const float* __restrict__ X,
                                                       bf16* __restrict__ hi,
                                                       bf16* __restrict__ lo) {
    int row = blockIdx.x;
    const float4* x4 = (const float4*)(X + (size_t)row * NN);
    float4 v[4];
    float ss = 0.f;
#pragma unroll
    for (int i = 0; i < 4; i++) {
        v[i] = x4[threadIdx.x + i * 256];
        ss += v[i].x * v[i].x + v[i].y * v[i].y + v[i].z * v[i].z + v[i].w * v[i].w;
    }
#pragma unroll
    for (int o = 16; o; o >>= 1) ss += __shfl_xor_sync(0xffffffffu, ss, o);
    __shared__ float wsum[8];
    int warp = threadIdx.x >> 5, lane = threadIdx.x & 31;
    if (lane == 0) wsum[warp] = ss;
    __syncthreads();
    float tot = 0.f;
#pragma unroll
    for (int w = 0; w < 8; w++) tot += wsum[w];
    float s = rsqrtf(tot * (1.0f / (float)NN));
#pragma unroll
    for (int i = 0; i < 4; i++) {
        float a = v[i].x * s, b = v[i].y * s, c = v[i].z * s, d = v[i].w * s;
        size_t off = (size_t)row * NN + (threadIdx.x + i * 256) * 4;
        bf16 h0, h1, h2, h3, l0, l1, l2, l3;
        split2(a, h0, l0); split2(b, h1, l1);
        split2(c, h2, l2); split2(d, h3, l3);
        *(__nv_bfloat162*)(hi + off)     = __nv_bfloat162(h0, h1);
        *(__nv_bfloat162*)(hi + off + 2) = __nv_bfloat162(h2, h3);
        *(__nv_bfloat162*)(lo + off)     = __nv_bfloat162(l0, l1);
        *(__nv_bfloat162*)(lo + off + 2) = __nv_bfloat162(l2, l3);
    }
}

// ---------------------------------------------------------------------------
// Transpose + split W [K, N] fp32 -> Wt hi/lo bf16 [N, K]
// ---------------------------------------------------------------------------
__global__ __launch_bounds__(256) void wsplit_kernel(const float* __restrict__ W,
                                                     bf16* __restrict__ hi,
                                                     bf16* __restrict__ lo) {
    __shared__ float t[32][33];
    int tx = threadIdx.x & 31, ty = threadIdx.x >> 5;
    int n0 = blockIdx.x * 32, k0 = blockIdx.y * 32;
#pragma unroll
    for (int i = 0; i < 4; i++)
        t[ty + i * 8][tx] = W[(size_t)(k0 + ty + i * 8) * NN + n0 + tx];
    __syncthreads();
#pragma unroll
    for (int i = 0; i < 4; i++) {
        float v = t[tx][ty + i * 8];
        bf16 h, l;
        split2(v, h, l);
        size_t off = (size_t)(n0 + ty + i * 8) * NN + k0 + tx;
        hi[off] = h;
        lo[off] = l;
    }
}

// ---------------------------------------------------------------------------
// Per-head RMSNorm over D=128.  q rows: norm + split -> Qh/Ql.
// k rows: norm in place (consumed by build_khl).
// ---------------------------------------------------------------------------
__global__ __launch_bounds__(256) void qknorm_split_kernel(const float* __restrict__ q,
                                                           float* __restrict__ k,
                                                           bf16* __restrict__ Qh,
                                                           bf16* __restrict__ Ql) {
    int gw = (int)((blockIdx.x * blockDim.x + threadIdx.x) >> 5);
    int lane = threadIdx.x & 31;
    bool isq = (gw < MM * HH);
    int row = isq ? gw : gw - MM * HH;
    const float* src = isq ? q : k;
    float4 a = ((const float4*)(src + (size_t)row * DD))[lane];
    float ss = a.x * a.x + a.y * a.y + a.z * a.z + a.w * a.w;
#pragma unroll
    for (int o = 16; o; o >>= 1) ss += __shfl_xor_sync(0xffffffffu, ss, o);
    float s = rsqrtf(ss * (1.0f / (float)DD));
    a.x *= s; a.y *= s; a.z *= s; a.w *= s;
    if (isq) {
        bf16 h0, h1, h2, h3, l0, l1, l2, l3;
        split2(a.x, h0, l0); split2(a.y, h1, l1);
        split2(a.z, h2, l2); split2(a.w, h3, l3);
        size_t off = (size_t)row * DD + lane * 4;
        *(__nv_bfloat162*)(Qh + off)     = __nv_bfloat162(h0, h1);
        *(__nv_bfloat162*)(Qh + off + 2) = __nv_bfloat162(h2, h3);
        *(__nv_bfloat162*)(Ql + off)     = __nv_bfloat162(l0, l1);
        *(__nv_bfloat162*)(Ql + off + 2) = __nv_bfloat162(l2, l3);
    } else {
        ((float4*)(k + (size_t)row * DD))[lane] = a;
    }
}

// ---------------------------------------------------------------------------
// Build K cache (combined) hi/lo: [h][kv][d]
// ---------------------------------------------------------------------------
__global__ __launch_bounds__(256) void build_khl(const float* __restrict__ cacheK,
                                                 const float* __restrict__ kproj,
                                                 bf16* __restrict__ Kh,
                                                 bf16* __restrict__ Kl) {
    size_t e = ((size_t)blockIdx.x * 256 + threadIdx.x) * 4;
    int h = (int)(e / ((size_t)KVLEN * DD));
    int rem = (int)(e % ((size_t)KVLEN * DD));
    int r = rem / DD, c = rem % DD;
    const float* src = (r < PP)
        ? cacheK + (((size_t)h * PP + r) * DD + c)
        : kproj + ((size_t)(r - PP) * NN + h * DD + c);
    float4 v = *(const float4*)src;
    bf16 h0, h1, h2, h3, l0, l1, l2, l3;
    split2(v.x, h0, l0); split2(v.y, h1, l1);
    split2(v.z, h2, l2); split2(v.w, h3, l3);
    *(__nv_bfloat162*)(Kh + e)     = __nv_bfloat162(h0, h1);
    *(__nv_bfloat162*)(Kh + e + 2) = __nv_bfloat162(h2, h3);
    *(__nv_bfloat162*)(Kl + e)     = __nv_bfloat162(l0, l1);
    *(__nv_bfloat162*)(Kl + e + 2) = __nv_bfloat162(l2, l3);
}

// ---------------------------------------------------------------------------
// Build V^T hi/lo: [h][d][kv]
// ---------------------------------------------------------------------------
__global__ __launch_bounds__(256) void build_vt(const float* __restrict__ cacheV,
                                                const float* __restrict__ vproj,
                                                bf16* __restrict__ Vh,
                                                bf16* __restrict__ Vl) {
    __shared__ float t[32][33];
    int tx = threadIdx.x & 31, ty = threadIdx.x >> 5;
    int kv0 = blockIdx.x * 32, d0 = blockIdx.y * 32, h = blockIdx.z;
#pragma unroll
    for (int i = 0; i < 4; i++) {
        int r = kv0 + ty + i * 8;
        int c = d0 + tx;
        float v = (r < PP)
            ? cacheV[((size_t)h * PP + r) * DD + c]
            : vproj[(size_t)(r - PP) * NN + h * DD + c];
        t[ty + i * 8][tx] = v;
    }
    __syncthreads();
#pragma unroll
    for (int i = 0; i < 4; i++) {
        int d = d0 + ty + i * 8;
        float v = t[tx][ty + i * 8];
        bf16 hh, ll;
        split2(v, hh, ll);
        size_t off = ((size_t)h * DD + d) * KVLEN + kv0 + tx;
        Vh[off] = hh;
        Vl[off] = ll;
    }
}

// ---------------------------------------------------------------------------
// bf16x3 GEMM (mma.sync m16n8k16), 3-slot / 2-in-flight cp.async pipeline,
// ONE __syncthreads per K-chunk. Term-major MMA order (no acc RAW chains).
// ---------------------------------------------------------------------------
template <int BN, int WN>
__global__ __launch_bounds__(256, 1) void gemm3(
    const bf16* __restrict__ Ah, const bf16* __restrict__ Al,
    const bf16* __restrict__ Bh, const bf16* __restrict__ Bl,
    float* __restrict__ C, int K, int lda, int ldb, int ldc,
    long long sA, long long sB, long long sC) {
    constexpr int BM = 128;
    constexpr int NFR = WN / 8;
    constexpr int PADB = 80;
    constexpr int STG = (2 * BM + 2 * BN) * PADB;
    extern __shared__ char smraw[];

    const int tid = threadIdx.x;
    const int lane = tid & 31, wid = tid >> 5;
    const int wr = wid >> 2, wc = wid & 3;
    const int m0 = blockIdx.y * BM, n0 = blockIdx.x * BN;
    Ah += (long long)blockIdx.z * sA;
    Al += (long long)blockIdx.z * sA;
    Bh += (long long)blockIdx.z * sB;
    Bl += (long long)blockIdx.z * sB;
    C += (long long)blockIdx.z * sC;

    float acc[4][NFR][4];
#pragma unroll
    for (int f = 0; f < 4; f++)
#pragma unroll
        for (int j = 0; j < NFR; j++)
#pragma unroll
            for (int x = 0; x < 4; x++) acc[f][j][x] = 0.f;

    const uint32_t sbase = smem_u32(smraw);
    const uint32_t aoff = (uint32_t)((wr * 64 + (lane & 15)) * PADB + (lane >> 4) * 16);
    const uint32_t boff = (uint32_t)((wc * WN + (lane & 7)) * PADB + ((lane >> 3) & 1) * 16);

    auto issue = [&](int slot, int k0) {
        uint32_t ba = sbase + slot * STG;
        const bf16* pAh = Ah + (size_t)m0 * lda + k0;
        const bf16* pAl = Al + (size_t)m0 * lda + k0;
#pragma unroll
        for (int i = tid; i < BM * 4; i += 256) {
            int r = i >> 2, cb = (i & 3) * 16;
            cp16(ba + r * PADB + cb, (const char*)(pAh + (size_t)r * lda) + cb);
            cp16(ba + BM * PADB + r * PADB + cb, (const char*)(pAl + (size_t)r * lda) + cb);
        }
        uint32_t bb = ba + 2 * BM * PADB;
        const bf16* pBh = Bh + (size_t)n0 * ldb + k0;
        const bf16* pBl = Bl + (size_t)n0 * ldb + k0;
#pragma unroll
        for (int i = tid; i < BN * 4; i += 256) {
            int r = i >> 2, cb = (i & 3) * 16;
            cp16(bb + r * PADB + cb, (const char*)(pBh + (size_t)r * ldb) + cb);
            cp16(bb + BN * PADB + r * PADB + cb, (const char*)(pBl + (size_t)r * ldb) + cb);
        }
        CP_COMMIT();
    };

    const int nch = K >> 5;
    issue(0, 0);
    if (nch > 1) issue(1, 32);

    for (int kc = 0; kc < nch; kc++) {
        if (kc + 1 < nch) { CP_WAIT1(); } else { CP_WAIT0(); }
        __syncthreads();
        if (kc + 2 < nch) issue((kc + 2) % 3, (kc + 2) << 5);

        const uint32_t aH = sbase + (kc % 3) * STG;
        const uint32_t aL = aH + BM * PADB;
        const uint32_t bH = aL + BM * PADB;
        const uint32_t bL = bH + BN * PADB;
#pragma unroll
        for (int ks = 0; ks < 2; ks++) {
            uint32_t ah[4][4], al[4][4];
#pragma unroll
            for (int f = 0; f < 4; f++) {
                uint32_t off = aoff + f * 16 * PADB + ks * 32;
                ldsm_x4(ah[f], aH + off);
                ldsm_x4(al[f], aL + off);
            }
#pragma unroll
            for (int j = 0; j < NFR; j++) {
                uint32_t off = boff + j * 8 * PADB + ks * 32;
                uint32_t bh[2], bl[2];
                ldsm_x2(bh, bH + off);
                ldsm_x2(bl, bL + off);
                // term-major: 4 independent MMAs between same-acc reuses
#pragma unroll
                for (int f = 0; f < 4; f++) MMA16816(acc[f][j], ah[f], bh);
#pragma unroll
                for (int f = 0; f < 4; f++) MMA16816(acc[f][j], ah[f], bl);
#pragma unroll
                for (int f = 0; f < 4; f++) MMA16816(acc[f][j], al[f], bh);
            }
        }
    }
    __syncthreads();

#pragma unroll
    for (int f = 0; f < 4; f++) {
        int row = m0 + wr * 64 + f * 16 + (lane >> 2);
#pragma unroll
        for (int j = 0; j < NFR; j++) {
            int col = n0 + wc * WN + j * 8 + (lane & 3) * 2;
            *(float2*)(C + (size_t)row * ldc + col) = make_float2(acc[f][j][0], acc[f][j][1]);
            *(float2*)(C + (size_t)(row + 8) * ldc + col) = make_float2(acc[f][j][2], acc[f][j][3]);
        }
    }
}

// ---------------------------------------------------------------------------
// Fused flash attention on mma.sync, bf16x3, term-major MMA order.
// Block: 128 q-rows x 1 head. 8 warps, each owns 16 rows. KV chunks of 64.
// ---------------------------------------------------------------------------
#define FA_KPAD 272
#define FA_VPAD 144
#define FA_QB (128 * FA_KPAD)
#define FA_KT (64 * FA_KPAD)
#define FA_VT (128 * FA_VPAD)
#define FA_STG (2 * FA_KT + 2 * FA_VT)
#define FA_SMEM (2 * FA_QB + 2 * FA_STG)   // 212992

__global__ __launch_bounds__(256, 1) void attn_fused(
    const bf16* __restrict__ Qh_, const bf16* __restrict__ Ql_,
    const bf16* __restrict__ Kh_, const bf16* __restrict__ Kl_,
    const bf16* __restrict__ Vh_, const bf16* __restrict__ Vl_,
    float* __restrict__ out) {
    extern __shared__ char sm[];
    const int tid = threadIdx.x, lane = tid & 31, wid = tid >> 5;
    const int m0 = blockIdx.x * 128, h = blockIdx.y;
    const uint32_t sb = smem_u32(sm);

#pragma unroll
    for (int i = tid; i < 128 * 16; i += 256) {
        int r = i >> 4, c = i & 15;
        size_t go = (size_t)(m0 + r) * NN + h * DD + c * 8;
        *(float4*)(sm + r * FA_KPAD + c * 16) = *(const float4*)(Qh_ + go);
        *(float4*)(sm + FA_QB + r * FA_KPAD + c * 16) = *(const float4*)(Ql_ + go);
    }

    const bf16* Khh = Kh_ + (size_t)h * KVLEN * DD;
    const bf16* Klh = Kl_ + (size_t)h * KVLEN * DD;
    const bf16* Vhh = Vh_ + (size_t)h * DD * KVLEN;
    const bf16* Vlh = Vl_ + (size_t)h * DD * KVLEN;

    auto issue = [&](int s, int kv0) {
        uint32_t kb = sb + 2 * FA_QB + s * FA_STG;
#pragma unroll
        for (int i = tid; i < 1024; i += 256) {
            int r = i >> 4, c = i & 15;
            size_t go = (size_t)(kv0 + r) * DD + c * 8;
            cp16(kb + r * FA_KPAD + c * 16, Khh + go);
            cp16(kb + FA_KT + r * FA_KPAD + c * 16, Klh + go);
        }
        uint32_t vb = kb + 2 * FA_KT;
#pragma unroll
        for (int i = tid; i < 1024; i += 256) {
            int r = i >> 3, c = i & 7;
            size_t go = (size_t)r * KVLEN + kv0 + c * 8;
            cp16(vb + r * FA_VPAD + c * 16, Vhh + go);
            cp16(vb + FA_VT + r * FA_VPAD + c * 16, Vlh + go);
        }
        CP_COMMIT();
    };

    float oacc[16][4];
#pragma unroll
    for (int j = 0; j < 16; j++)
#pragma unroll
        for (int x = 0; x < 4; x++) oacc[j][x] = 0.f;
    float mrow0 = -INFINITY, mrow8 = -INFINITY;
    float lrow0 = 0.f, lrow8 = 0.f;

    const uint32_t qoff = (uint32_t)((wid * 16 + (lane & 15)) * FA_KPAD + (lane >> 4) * 16);
    const uint32_t koff = (uint32_t)((lane & 7) * FA_KPAD + ((lane >> 3) & 1) * 16);
    const uint32_t voff = (uint32_t)((lane & 7) * FA_VPAD + ((lane >> 3) & 1) * 16);

    issue(0, 0);

    for (int ch = 0; ch < KVLEN / 64; ch++) {
        const int s = ch & 1;
        if (ch + 1 < KVLEN / 64) {
            issue(s ^ 1, (ch + 1) * 64);
            CP_WAIT1();
        } else {
            CP_WAIT0();
        }
        __syncthreads();

        const uint32_t bKh = sb + 2 * FA_QB + s * FA_STG;
        const uint32_t bKl = bKh + FA_KT;
        const uint32_t bVh = bKh + 2 * FA_KT;
        const uint32_t bVl = bVh + FA_VT;

        // S = Q @ K^T, term-major over 8 j-tiles
        float sacc[8][4];
#pragma unroll
        for (int j = 0; j < 8; j++)
#pragma unroll
            for (int x = 0; x < 4; x++) sacc[j][x] = 0.f;
#pragma unroll
        for (int ks = 0; ks < 8; ks++) {
            uint32_t qh[4], ql[4];
            ldsm_x4(qh, sb + qoff + ks * 32);
            ldsm_x4(ql, sb + FA_QB + qoff + ks * 32);
            uint32_t kh[8][2], kl[8][2];
#pragma unroll
            for (int j = 0; j < 8; j++) {
                uint32_t off = koff + j * 8 * FA_KPAD + ks * 32;
                ldsm_x2(kh[j], bKh + off);
                ldsm_x2(kl[j], bKl + off);
            }
#pragma unroll
            for (int j = 0; j < 8; j++) MMA16816(sacc[j], qh, kh[j]);
#pragma unroll
            for (int j = 0; j < 8; j++) MMA16816(sacc[j], qh, kl[j]);
#pragma unroll
            for (int j = 0; j < 8; j++) MMA16816(sacc[j], ql, kh[j]);
        }

        // Online softmax (rows r = lane>>2 and r+8)
        float mx0 = -INFINITY, mx8 = -INFINITY;
#pragma unroll
        for (int j = 0; j < 8; j++) {
            mx0 = fmaxf(mx0, fmaxf(sacc[j][0], sacc[j][1]));
            mx8 = fmaxf(mx8, fmaxf(sacc[j][2], sacc[j][3]));
        }
        mx0 = fmaxf(mx0, __shfl_xor_sync(0xffffffffu, mx0, 1));
        mx0 = fmaxf(mx0, __shfl_xor_sync(0xffffffffu, mx0, 2));
        mx8 = fmaxf(mx8, __shfl_xor_sync(0xffffffffu, mx8, 1));
        mx8 = fmaxf(mx8, __shfl_xor_sync(0xffffffffu, mx8, 2));
        float mn0 = fmaxf(mrow0, mx0), mn8 = fmaxf(mrow8, mx8);
        float sc0 = __expf(mrow0 - mn0), sc8 = __expf(mrow8 - mn8);
        mrow0 = mn0; mrow8 = mn8;
        float ps0 = 0.f, ps8 = 0.f;
#pragma unroll
        for (int j = 0; j < 8; j++) {
            sacc[j][0] = __expf(sacc[j][0] - mn0);
            sacc[j][1] = __expf(sacc[j][1] - mn0);
            sacc[j][2] = __expf(sacc[j][2] - mn8);
            sacc[j][3] = __expf(sacc[j][3] - mn8);
            ps0 += sacc[j][0] + sacc[j][1];
            ps8 += sacc[j][2] + sacc[j][3];
        }
        lrow0 = lrow0 * sc0 + ps0;
        lrow8 = lrow8 * sc8 + ps8;
#pragma unroll
        for (int j = 0; j < 16; j++) {
            oacc[j][0] *= sc0; oacc[j][1] *= sc0;
            oacc[j][2] *= sc8; oacc[j][3] *= sc8;
        }

        // P fragments: hi/lo split in regs
        uint32_t ph[4][4], pl[4][4];
#pragma unroll
        for (int kk = 0; kk < 4; kk++) {
            ph[kk][0] = packsplit_hi(sacc[2 * kk][0], sacc[2 * kk][1]);
            ph[kk][1] = packsplit_hi(sacc[2 * kk][2], sacc[2 * kk][3]);
            ph[kk][2] = packsplit_hi(sacc[2 * kk + 1][0], sacc[2 * kk + 1][1]);
            ph[kk][3] = packsplit_hi(sacc[2 * kk + 1][2], sacc[2 * kk + 1][3]);
            pl[kk][0] = packsplit_lo(sacc[2 * kk][0], sacc[2 * kk][1]);
            pl[kk][1] = packsplit_lo(sacc[2 * kk][2], sacc[2 * kk][3]);
            pl[kk][2] = packsplit_lo(sacc[2 * kk + 1][0], sacc[2 * kk + 1][1]);
            pl[kk][3] = packsplit_lo(sacc[2 * kk + 1][2], sacc[2 * kk + 1][3]);
        }

        // O += P @ V^T, term-major in halves of 8 j-tiles
#pragma unroll
        for (int kk = 0; kk < 4; kk++) {
#pragma unroll
            for (int jh = 0; jh < 2; jh++) {
                uint32_t vh[8][2], vl[8][2];
#pragma unroll
                for (int j = 0; j < 8; j++) {
                    uint32_t off = voff + (jh * 8 + j) * 8 * FA_VPAD + kk * 32;
                    ldsm_x2(vh[j], bVh + off);
                    ldsm_x2(vl[j], bVl + off);
                }
#pragma unroll
                for (int j = 0; j < 8; j++) MMA16816(oacc[jh * 8 + j], ph[kk], vh[j]);
#pragma unroll
                for (int j = 0; j < 8; j++) MMA16816(oacc[jh * 8 + j], ph[kk], vl[j]);
#pragma unroll
                for (int j = 0; j < 8; j++) MMA16816(oacc[jh * 8 + j], pl[kk], vh[j]);
            }
        }
        __syncthreads();
    }

    lrow0 += __shfl_xor_sync(0xffffffffu, lrow0, 1);
    lrow0 += __shfl_xor_sync(0xffffffffu, lrow0, 2);
    lrow8 += __shfl_xor_sync(0xffffffffu, lrow8, 1);
    lrow8 += __shfl_xor_sync(0xffffffffu, lrow8, 2);
    float inv0 = 1.0f / lrow0, inv8 = 1.0f / lrow8;
    int r0 = m0 + wid * 16 + (lane >> 2);
#pragma unroll
    for (int j = 0; j < 16; j++) {
        int col = h * DD + j * 8 + (lane & 3) * 2;
        *(float2*)(out + (size_t)r0 * NN + col) =
            make_float2(oacc[j][0] * inv0, oacc[j][1] * inv0);
        *(float2*)(out + (size_t)(r0 + 8) * NN + col) =
            make_float2(oacc[j][2] * inv8, oacc[j][3] * inv8);
    }
}

// ---------------------------------------------------------------------------
extern "C" void kernel_launch(void* const* d_in, const int* in_sizes, int n_in,
                              void* d_out, int out_size) {
    const float* X  = (const float*)d_in[0];
    const float* Wq = (const float*)d_in[1];
    const float* Wk = (const float*)d_in[2];
    const float* Wv = (const float*)d_in[3];
    const float* cK = (const float*)d_in[4];
    const float* cV = (const float*)d_in[5];
    float* out = (float*)d_out;

    float* qkv;
    bf16 *Xhi, *Xlo, *Wthi, *Wtlo, *Qhi, *Qlo, *Khi, *Klo, *Vthi, *Vtlo;
    cudaGetSymbolAddress((void**)&qkv, g_qkv);
    cudaGetSymbolAddress((void**)&Xhi, g_Xhi);
    cudaGetSymbolAddress((void**)&Xlo, g_Xlo);
    cudaGetSymbolAddress((void**)&Wthi, g_Wthi);
    cudaGetSymbolAddress((void**)&Wtlo, g_Wtlo);
    cudaGetSymbolAddress((void**)&Qhi, g_Qhi);
    cudaGetSymbolAddress((void**)&Qlo, g_Qlo);
    cudaGetSymbolAddress((void**)&Khi, g_Khi);
    cudaGetSymbolAddress((void**)&Klo, g_Klo);
    cudaGetSymbolAddress((void**)&Vthi, g_Vthi);
    cudaGetSymbolAddress((void**)&Vtlo, g_Vtlo);

    float* q = qkv;
    float* k = qkv + (size_t)MN;
    float* v = qkv + 2ull * MN;

    const int SM256 = 3 * (2 * 128 + 2 * 256) * 80;   // 184320 (3 slots)
    cudaFuncSetAttribute(gemm3<256, 64>, cudaFuncAttributeMaxDynamicSharedMemorySize, SM256);
    cudaFuncSetAttribute(attn_fused, cudaFuncAttributeMaxDynamicSharedMemorySize, FA_SMEM);

    // 1) RMSNorm X + split (fused)
    rmsnorm_split_x<<<MM, 256>>>(X, Xhi, Xlo);

    // 2) W transpose+split
    dim3 wgrid(NN / 32, NN / 32);
    wsplit_kernel<<<wgrid, 256>>>(Wq, Wthi + 0ull * NN * NN, Wtlo + 0ull * NN * NN);
    wsplit_kernel<<<wgrid, 256>>>(Wk, Wthi + 1ull * NN * NN, Wtlo + 1ull * NN * NN);
    wsplit_kernel<<<wgrid, 256>>>(Wv, Wthi + 2ull * NN * NN, Wtlo + 2ull * NN * NN);

    // 3) QKV = Xn @ W  (batch 3)
    gemm3<256, 64><<<dim3(NN / 256, MM / 128, 3), 256, SM256>>>(
        Xhi, Xlo, Wthi, Wtlo, qkv, NN, NN, NN, NN,
        0LL, (long long)NN * NN, (long long)MN);

    // 4) qk-norm (q: norm+split to Qhi/Qlo; k: norm in place)
    qknorm_split_kernel<<<(2 * MM * HH * 32) / 256, 256>>>(q, k, Qhi, Qlo);

    // 5) combined KV cache splits
    build_khl<<<(int)((size_t)HH * KVLEN * DD / 1024), 256>>>(cK, k, Khi, Klo);
    build_vt<<<dim3(KVLEN / 32, DD / 32, HH), 256>>>(cV, v, Vthi, Vtlo);

    // 6) fused flash attention -> d_out
    attn_fused<<<dim3(MM / 128, HH), 256, FA_SMEM>>>(
        Qhi, Qlo, Khi, Klo, Vthi, Vtlo, out);
}